// round 1
// baseline (speedup 1.0000x reference)
#include <cuda_runtime.h>

#define DIM 768
#define NH 12
#define DH 64
#define BATCH 4
#define SEQ 1024
#define ROWS (BATCH*SEQ)            // 4096
#define SCALE_ATT 0.125f            // 64^-0.5

// ---------------- scratch (no allocations allowed) ----------------
__device__ float g_xn[ROWS*DIM];
__device__ float g_q [ROWS*DIM];
__device__ float g_k [ROWS*DIM];
__device__ float g_v [ROWS*DIM];
__device__ float g_att[ROWS*DIM];

// ---------------- LayerNorm (unbiased std, ddof=1) ----------------
__global__ void __launch_bounds__(256) ln_kernel(const float* __restrict__ x,
                                                 float* __restrict__ xn) {
    int row = blockIdx.x;
    const float* xr = x + (size_t)row * DIM;
    int t = threadIdx.x;
    float v0 = xr[t], v1 = xr[t + 256], v2 = xr[t + 512];
    float s  = v0 + v1 + v2;
    float sq = v0*v0 + v1*v1 + v2*v2;
    #pragma unroll
    for (int o = 16; o; o >>= 1) {
        s  += __shfl_xor_sync(0xffffffffu, s,  o);
        sq += __shfl_xor_sync(0xffffffffu, sq, o);
    }
    __shared__ float rs[8], rq[8];
    int w = t >> 5, l = t & 31;
    if (l == 0) { rs[w] = s; rq[w] = sq; }
    __syncthreads();
    if (w == 0) {
        s  = (l < 8) ? rs[l] : 0.f;
        sq = (l < 8) ? rq[l] : 0.f;
        #pragma unroll
        for (int o = 4; o; o >>= 1) {
            s  += __shfl_xor_sync(0xffffffffu, s,  o);
            sq += __shfl_xor_sync(0xffffffffu, sq, o);
        }
        if (l == 0) { rs[0] = s; rq[0] = sq; }
    }
    __syncthreads();
    s = rs[0]; sq = rq[0];
    float mean = s * (1.f / DIM);
    float var  = (sq - (float)DIM * mean * mean) * (1.f / (DIM - 1));
    float inv  = rsqrtf(var);
    float* xo = xn + (size_t)row * DIM;
    xo[t]       = (v0 - mean) * inv;
    xo[t + 256] = (v1 - mean) * inv;
    xo[t + 512] = (v2 - mean) * inv;
}

// ---------------- SGEMM-NT: C[M,N] = A[M,K] * W[N,K]^T + bias (+res) ------
#define BM 128
#define BN 64
#define BK 16
__global__ void __launch_bounds__(256) gemm_nt(const float* __restrict__ A,
                                               const float* __restrict__ W,
                                               const float* __restrict__ bias,
                                               const float* __restrict__ res,
                                               float* __restrict__ C) {
    __shared__ float As[BK][BM + 4];   // padded: STS 2-way max, LDS.128 aligned
    __shared__ float Bs[BK][BN + 4];
    int t  = threadIdx.x;
    int tx = t & 15, ty = t >> 4;
    int bm0 = blockIdx.y * BM, bn0 = blockIdx.x * BN;
    int lr = t >> 2;                  // 0..63
    int lk = (t & 3) * 4;             // 0,4,8,12
    const float* Ap  = A + (size_t)(bm0 + lr) * DIM + lk;
    const float* Ap2 = Ap + (size_t)64 * DIM;
    const float* Wp  = W + (size_t)(bn0 + lr) * DIM + lk;

    float acc[8][4] = {};
    for (int kt = 0; kt < DIM; kt += BK) {
        float4 a0 = *(const float4*)(Ap  + kt);
        float4 a1 = *(const float4*)(Ap2 + kt);
        float4 b0 = *(const float4*)(Wp  + kt);
        As[lk + 0][lr]      = a0.x; As[lk + 1][lr]      = a0.y;
        As[lk + 2][lr]      = a0.z; As[lk + 3][lr]      = a0.w;
        As[lk + 0][lr + 64] = a1.x; As[lk + 1][lr + 64] = a1.y;
        As[lk + 2][lr + 64] = a1.z; As[lk + 3][lr + 64] = a1.w;
        Bs[lk + 0][lr] = b0.x; Bs[lk + 1][lr] = b0.y;
        Bs[lk + 2][lr] = b0.z; Bs[lk + 3][lr] = b0.w;
        __syncthreads();
        #pragma unroll
        for (int kk = 0; kk < BK; kk++) {
            float4 x0 = *(const float4*)&As[kk][ty * 8];
            float4 x1 = *(const float4*)&As[kk][ty * 8 + 4];
            float4 y  = *(const float4*)&Bs[kk][tx * 4];
            float a[8] = {x0.x, x0.y, x0.z, x0.w, x1.x, x1.y, x1.z, x1.w};
            float b[4] = {y.x, y.y, y.z, y.w};
            #pragma unroll
            for (int i = 0; i < 8; i++)
                #pragma unroll
                for (int j = 0; j < 4; j++)
                    acc[i][j] = fmaf(a[i], b[j], acc[i][j]);
        }
        __syncthreads();
    }
    #pragma unroll
    for (int i = 0; i < 8; i++) {
        int row = bm0 + ty * 8 + i;
        size_t o = (size_t)row * DIM + bn0 + tx * 4;
        #pragma unroll
        for (int j = 0; j < 4; j++) {
            float v = acc[i][j] + bias[bn0 + tx * 4 + j];
            if (res) v += res[o + j];
            C[o + j] = v;
        }
    }
}

// ---------------- Fused flash attention (fp32, 64x64 tiles) ----------------
// grid: (SEQ/64, NH, BATCH), block 256
// smem: sQT[64d][64r] | sS[64][65] | sKV (KT: [d][kr]; V: [k][c]) stride 64
#define SMEM_ATTN ((4096 + 4160 + 4096) * 4)
__global__ void __launch_bounds__(256) attn_kernel(const float* __restrict__ Q,
                                                   const float* __restrict__ K,
                                                   const float* __restrict__ V,
                                                   float* __restrict__ O) {
    extern __shared__ float sm[];
    float* sQT = sm;                 // 4096: [d*64 + qrow]
    float* sS  = sm + 4096;          // 4160: [r*65 + c]
    float* sKV = sm + 8256;          // 4096: KT [d*64 + kr] / V [k*64 + c]

    int qt = blockIdx.x, h = blockIdx.y, b = blockIdx.z;
    int t  = threadIdx.x;
    int tx = t & 15, ty = t >> 4;    // phase A micro-tile coords
    int r  = t >> 2, q4 = t & 3;     // phase B/C row mapping
    int d0 = q4 * 16;

    // load Q tile transposed: thread owns row r, cols d0..d0+15
    {
        int qrow = qt * 64 + r;
        const float* qp = Q + (size_t)(b * SEQ + qrow) * DIM + h * DH + d0;
        #pragma unroll
        for (int u = 0; u < 4; u++) {
            float4 v = *(const float4*)(qp + 4 * u);
            sQT[(d0 + 4*u + 0) * 64 + r] = v.x;
            sQT[(d0 + 4*u + 1) * 64 + r] = v.y;
            sQT[(d0 + 4*u + 2) * 64 + r] = v.z;
            sQT[(d0 + 4*u + 3) * 64 + r] = v.w;
        }
    }

    float m_run = -1e30f, l_run = 0.f;
    float o[16];
    #pragma unroll
    for (int i = 0; i < 16; i++) o[i] = 0.f;

    for (int kt = 0; kt < SEQ / 64; kt++) {
        int krow = kt * 64 + r;
        const float* kp = K + (size_t)(b * SEQ + krow) * DIM + h * DH + d0;
        // load K transposed
        #pragma unroll
        for (int u = 0; u < 4; u++) {
            float4 v = *(const float4*)(kp + 4 * u);
            sKV[(d0 + 4*u + 0) * 64 + r] = v.x;
            sKV[(d0 + 4*u + 1) * 64 + r] = v.y;
            sKV[(d0 + 4*u + 2) * 64 + r] = v.z;
            sKV[(d0 + 4*u + 3) * 64 + r] = v.w;
        }
        __syncthreads();

        // phase A: S = Q K^T  (4x4 micro-tile per thread)
        float acc[4][4] = {};
        #pragma unroll 8
        for (int d = 0; d < 64; d++) {
            float4 qf = *(const float4*)&sQT[d * 64 + ty * 4];
            float4 kf = *(const float4*)&sKV[d * 64 + tx * 4];
            float qa[4] = {qf.x, qf.y, qf.z, qf.w};
            float ka[4] = {kf.x, kf.y, kf.z, kf.w};
            #pragma unroll
            for (int i = 0; i < 4; i++)
                #pragma unroll
                for (int j = 0; j < 4; j++)
                    acc[i][j] = fmaf(qa[i], ka[j], acc[i][j]);
        }
        #pragma unroll
        for (int i = 0; i < 4; i++)
            #pragma unroll
            for (int j = 0; j < 4; j++)
                sS[(ty * 4 + i) * 65 + tx * 4 + j] = acc[i][j] * SCALE_ATT;
        __syncthreads();

        // phase B: online softmax for row r (4 threads/row, 16 cols each)
        float* srow = &sS[r * 65 + d0];
        float mx = -1e30f;
        #pragma unroll
        for (int i = 0; i < 16; i++) mx = fmaxf(mx, srow[i]);
        mx = fmaxf(mx, __shfl_xor_sync(0xffffffffu, mx, 1));
        mx = fmaxf(mx, __shfl_xor_sync(0xffffffffu, mx, 2));
        float m_new = fmaxf(m_run, mx);
        float alpha = __expf(m_run - m_new);
        float lsum = 0.f;
        #pragma unroll
        for (int i = 0; i < 16; i++) {
            float p = __expf(srow[i] - m_new);
            srow[i] = p;
            lsum += p;
        }
        lsum += __shfl_xor_sync(0xffffffffu, lsum, 1);
        lsum += __shfl_xor_sync(0xffffffffu, lsum, 2);
        l_run = l_run * alpha + lsum;
        m_run = m_new;
        #pragma unroll
        for (int i = 0; i < 16; i++) o[i] *= alpha;

        // load V (natural layout) into sKV — phase A readers are past the barrier
        const float* vp = V + (size_t)(b * SEQ + krow) * DIM + h * DH + d0;
        #pragma unroll
        for (int u = 0; u < 4; u++) {
            float4 v = *(const float4*)(vp + 4 * u);
            *(float4*)&sKV[r * 64 + d0 + 4 * u] = v;
        }
        __syncthreads();

        // phase C: O += P V  (row r, cols d0..d0+15)
        #pragma unroll 8
        for (int k = 0; k < 64; k++) {
            float p = sS[r * 65 + k];
            #pragma unroll
            for (int u = 0; u < 4; u++) {
                float4 v = *(const float4*)&sKV[k * 64 + d0 + 4 * u];
                o[4*u + 0] = fmaf(p, v.x, o[4*u + 0]);
                o[4*u + 1] = fmaf(p, v.y, o[4*u + 1]);
                o[4*u + 2] = fmaf(p, v.z, o[4*u + 2]);
                o[4*u + 3] = fmaf(p, v.w, o[4*u + 3]);
            }
        }
        __syncthreads();
    }

    // epilogue
    float inv = 1.f / l_run;
    int orow = b * SEQ + qt * 64 + r;
    float* op = O + (size_t)orow * DIM + h * DH + d0;
    #pragma unroll
    for (int u = 0; u < 4; u++) {
        float4 v;
        v.x = o[4*u + 0] * inv; v.y = o[4*u + 1] * inv;
        v.z = o[4*u + 2] * inv; v.w = o[4*u + 3] * inv;
        *(float4*)(op + 4 * u) = v;
    }
}

// ---------------- launch ----------------
extern "C" void kernel_launch(void* const* d_in, const int* in_sizes, int n_in,
                              void* d_out, int out_size) {
    const float* x  = (const float*)d_in[0];
    const float* qw = (const float*)d_in[1];
    const float* kw = (const float*)d_in[2];
    const float* vw = (const float*)d_in[3];
    const float* qb = (const float*)d_in[4];
    const float* kb = (const float*)d_in[5];
    const float* vb = (const float*)d_in[6];
    const float* pw = (const float*)d_in[7];
    const float* pb = (const float*)d_in[8];
    float* out = (float*)d_out;

    float *xn, *q, *k, *v, *att;
    cudaGetSymbolAddress((void**)&xn,  g_xn);
    cudaGetSymbolAddress((void**)&q,   g_q);
    cudaGetSymbolAddress((void**)&k,   g_k);
    cudaGetSymbolAddress((void**)&v,   g_v);
    cudaGetSymbolAddress((void**)&att, g_att);

    cudaFuncSetAttribute(attn_kernel,
                         cudaFuncAttributeMaxDynamicSharedMemorySize, SMEM_ATTN);

    ln_kernel<<<ROWS, 256>>>(x, xn);

    dim3 ggrid(DIM / BN, ROWS / BM);   // (12, 32)
    gemm_nt<<<ggrid, 256>>>(xn, qw, qb, nullptr, q);
    gemm_nt<<<ggrid, 256>>>(xn, kw, kb, nullptr, k);
    gemm_nt<<<ggrid, 256>>>(xn, vw, vb, nullptr, v);

    attn_kernel<<<dim3(SEQ / 64, NH, BATCH), 256, SMEM_ATTN>>>(q, k, v, att);

    gemm_nt<<<ggrid, 256>>>(att, pw, pb, x, out);   // proj + bias + residual
}

// round 2
// speedup vs baseline: 3.1164x; 3.1164x over previous
#include <cuda_runtime.h>
#include <cstdint>

#define DIM 768
#define NH 12
#define DH 64
#define BATCH 4
#define SEQ 1024
#define ROWS (BATCH*SEQ)            // 4096
#define SCALE_ATT 0.125f            // 64^-0.5

// ---------------- scratch (no allocations allowed) ----------------
__device__ float g_xn[ROWS*DIM];
__device__ float g_q [ROWS*DIM];
__device__ float g_k [ROWS*DIM];
__device__ float g_v [ROWS*DIM];
__device__ float g_att[ROWS*DIM];

// ---------------- tf32 helpers ----------------
__device__ __forceinline__ uint32_t f2tf32(float x) {
    uint32_t r;
    asm("cvt.rna.tf32.f32 %0, %1;" : "=r"(r) : "f"(x));
    return r;
}
__device__ __forceinline__ float f2tf32f(float x) {
    return __uint_as_float(f2tf32(x));
}
__device__ __forceinline__ void mma_tf32(float* d, const uint32_t* a, const uint32_t* b) {
    asm volatile(
        "mma.sync.aligned.m16n8k8.row.col.f32.tf32.tf32.f32 "
        "{%0,%1,%2,%3}, {%4,%5,%6,%7}, {%8,%9}, {%0,%1,%2,%3};\n"
        : "+f"(d[0]), "+f"(d[1]), "+f"(d[2]), "+f"(d[3])
        : "r"(a[0]), "r"(a[1]), "r"(a[2]), "r"(a[3]), "r"(b[0]), "r"(b[1]));
}

// ---------------- LayerNorm (unbiased std, ddof=1) ----------------
__global__ void __launch_bounds__(256) ln_kernel(const float* __restrict__ x,
                                                 float* __restrict__ xn) {
    int row = blockIdx.x;
    const float* xr = x + (size_t)row * DIM;
    int t = threadIdx.x;
    float v0 = xr[t], v1 = xr[t + 256], v2 = xr[t + 512];
    float s  = v0 + v1 + v2;
    float sq = v0*v0 + v1*v1 + v2*v2;
    #pragma unroll
    for (int o = 16; o; o >>= 1) {
        s  += __shfl_xor_sync(0xffffffffu, s,  o);
        sq += __shfl_xor_sync(0xffffffffu, sq, o);
    }
    __shared__ float rs[8], rq[8];
    int w = t >> 5, l = t & 31;
    if (l == 0) { rs[w] = s; rq[w] = sq; }
    __syncthreads();
    if (w == 0) {
        s  = (l < 8) ? rs[l] : 0.f;
        sq = (l < 8) ? rq[l] : 0.f;
        #pragma unroll
        for (int o = 4; o; o >>= 1) {
            s  += __shfl_xor_sync(0xffffffffu, s,  o);
            sq += __shfl_xor_sync(0xffffffffu, sq, o);
        }
        if (l == 0) { rs[0] = s; rq[0] = sq; }
    }
    __syncthreads();
    s = rs[0]; sq = rq[0];
    float mean = s * (1.f / DIM);
    float var  = (sq - (float)DIM * mean * mean) * (1.f / (DIM - 1));
    float inv  = rsqrtf(var);
    float* xo = xn + (size_t)row * DIM;
    xo[t]       = (v0 - mean) * inv;
    xo[t + 256] = (v1 - mean) * inv;
    xo[t + 512] = (v2 - mean) * inv;
}

// ---------------- TF32 tensor-core GEMM-NT --------------------------------
// C[M,N] = A[M,K] @ W[N,K]^T + bias (+res).  BM=128 BN=64 BK=32, 256 thr.
// Warp grid 4(m) x 2(n); warp tile 32x32 = 2 m-frags x 4 n-frags of m16n8k8.
#define GSTR 36   // smem stride: (g*36+t)%32 = (4g+t)%32, conflict-free frag LDS
__global__ void __launch_bounds__(256) gemm_tc(const float* __restrict__ A,
                                               const float* __restrict__ W,
                                               const float* __restrict__ bias,
                                               const float* __restrict__ res,
                                               float* __restrict__ C) {
    __shared__ float As[128][GSTR];
    __shared__ float Bs[64][GSTR];
    int tid  = threadIdx.x;
    int lane = tid & 31, wid = tid >> 5;
    int g = lane >> 2, tq = lane & 3;
    int wm = (wid >> 1) * 32, wn = (wid & 1) * 32;
    int bm0 = blockIdx.y * 128, bn0 = blockIdx.x * 64;

    int lrA = tid >> 1, lkA = (tid & 1) * 16;   // A: 128 rows x 32k, 16 f/thr
    int lrB = tid >> 2, lkB = (tid & 3) * 8;    // W: 64 rows x 32k,  8 f/thr
    const float* Ap = A + (size_t)(bm0 + lrA) * DIM + lkA;
    const float* Wp = W + (size_t)(bn0 + lrB) * DIM + lkB;

    float acc[2][4][4] = {};

    for (int kt = 0; kt < DIM; kt += 32) {
        float4 av[4], bv[2];
        #pragma unroll
        for (int u = 0; u < 4; u++) av[u] = *(const float4*)(Ap + kt + 4*u);
        #pragma unroll
        for (int u = 0; u < 2; u++) bv[u] = *(const float4*)(Wp + kt + 4*u);
        __syncthreads();
        #pragma unroll
        for (int u = 0; u < 4; u++) {
            As[lrA][lkA + 4*u + 0] = f2tf32f(av[u].x);
            As[lrA][lkA + 4*u + 1] = f2tf32f(av[u].y);
            As[lrA][lkA + 4*u + 2] = f2tf32f(av[u].z);
            As[lrA][lkA + 4*u + 3] = f2tf32f(av[u].w);
        }
        #pragma unroll
        for (int u = 0; u < 2; u++) {
            Bs[lrB][lkB + 4*u + 0] = f2tf32f(bv[u].x);
            Bs[lrB][lkB + 4*u + 1] = f2tf32f(bv[u].y);
            Bs[lrB][lkB + 4*u + 2] = f2tf32f(bv[u].z);
            Bs[lrB][lkB + 4*u + 3] = f2tf32f(bv[u].w);
        }
        __syncthreads();

        #pragma unroll
        for (int k0 = 0; k0 < 32; k0 += 8) {
            uint32_t a[2][4], b[4][2];
            #pragma unroll
            for (int i = 0; i < 2; i++) {
                int r = wm + 16*i + g;
                a[i][0] = __float_as_uint(As[r    ][k0 + tq]);
                a[i][1] = __float_as_uint(As[r + 8][k0 + tq]);
                a[i][2] = __float_as_uint(As[r    ][k0 + tq + 4]);
                a[i][3] = __float_as_uint(As[r + 8][k0 + tq + 4]);
            }
            #pragma unroll
            for (int j = 0; j < 4; j++) {
                int n = wn + 8*j + g;
                b[j][0] = __float_as_uint(Bs[n][k0 + tq]);
                b[j][1] = __float_as_uint(Bs[n][k0 + tq + 4]);
            }
            #pragma unroll
            for (int i = 0; i < 2; i++)
                #pragma unroll
                for (int j = 0; j < 4; j++)
                    mma_tf32(acc[i][j], a[i], b[j]);
        }
    }

    #pragma unroll
    for (int i = 0; i < 2; i++) {
        int row = bm0 + wm + 16*i + g;
        #pragma unroll
        for (int j = 0; j < 4; j++) {
            int col = bn0 + wn + 8*j + 2*tq;
            float bx = bias[col], by = bias[col + 1];
            size_t o0 = (size_t)row * DIM + col;
            size_t o1 = (size_t)(row + 8) * DIM + col;
            float2 r0 = make_float2(acc[i][j][0] + bx, acc[i][j][1] + by);
            float2 r1 = make_float2(acc[i][j][2] + bx, acc[i][j][3] + by);
            if (res) {
                float2 e0 = *(const float2*)(res + o0);
                float2 e1 = *(const float2*)(res + o1);
                r0.x += e0.x; r0.y += e0.y; r1.x += e1.x; r1.y += e1.y;
            }
            *(float2*)(C + o0) = r0;
            *(float2*)(C + o1) = r1;
        }
    }
}

// ---------------- TF32 tensor-core flash attention -------------------------
// grid (SEQ/64, NH, BATCH), 128 threads (4 warps). Warp w owns Q rows
// [w*16, w*16+16). S and O accumulators live in mma C-fragments; softmax in
// registers via quad shuffles; P round-trips through a per-warp smem region.
#define ASTR 68   // (g*68+t)%32 = (4g+t)%32, conflict-free
#define SMEM_ATTN (4 * 64 * ASTR * 4)
__global__ void __launch_bounds__(128) attn_tc(const float* __restrict__ Q,
                                               const float* __restrict__ K,
                                               const float* __restrict__ V,
                                               float* __restrict__ O) {
    extern __shared__ float sm[];
    float* sQ = sm;
    float* sK = sm + 64 * ASTR;
    float* sV = sm + 2 * 64 * ASTR;
    float* sP = sm + 3 * 64 * ASTR;

    int qt = blockIdx.x, h = blockIdx.y, b = blockIdx.z;
    int tid = threadIdx.x;
    int lane = tid & 31, wid = tid >> 5;
    int g = lane >> 2, tq = lane & 3;
    int m0 = wid * 16;

    int lr = tid >> 1, ld = (tid & 1) * 32;   // loader: row, 32-float half

    // load Q tile (scale folded in; exact power of 2)
    {
        const float* qp = Q + (size_t)(b * SEQ + qt * 64 + lr) * DIM + h * DH + ld;
        #pragma unroll
        for (int u = 0; u < 8; u++) {
            float4 v = *(const float4*)(qp + 4*u);
            sQ[lr * ASTR + ld + 4*u + 0] = f2tf32f(v.x * SCALE_ATT);
            sQ[lr * ASTR + ld + 4*u + 1] = f2tf32f(v.y * SCALE_ATT);
            sQ[lr * ASTR + ld + 4*u + 2] = f2tf32f(v.z * SCALE_ATT);
            sQ[lr * ASTR + ld + 4*u + 3] = f2tf32f(v.w * SCALE_ATT);
        }
    }

    float m0run = -1e30f, m1run = -1e30f, l0run = 0.f, l1run = 0.f;
    float o[8][4] = {};

    for (int kt = 0; kt < SEQ / 64; kt++) {
        __syncthreads();   // previous iteration's reads of sK/sV done
        {
            int krow = kt * 64 + lr;
            const float* kp = K + (size_t)(b * SEQ + krow) * DIM + h * DH + ld;
            const float* vp = V + (size_t)(b * SEQ + krow) * DIM + h * DH + ld;
            #pragma unroll
            for (int u = 0; u < 8; u++) {
                float4 kv = *(const float4*)(kp + 4*u);
                float4 vv = *(const float4*)(vp + 4*u);
                sK[lr * ASTR + ld + 4*u + 0] = f2tf32f(kv.x);
                sK[lr * ASTR + ld + 4*u + 1] = f2tf32f(kv.y);
                sK[lr * ASTR + ld + 4*u + 2] = f2tf32f(kv.z);
                sK[lr * ASTR + ld + 4*u + 3] = f2tf32f(kv.w);
                sV[lr * ASTR + ld + 4*u + 0] = f2tf32f(vv.x);
                sV[lr * ASTR + ld + 4*u + 1] = f2tf32f(vv.y);
                sV[lr * ASTR + ld + 4*u + 2] = f2tf32f(vv.z);
                sV[lr * ASTR + ld + 4*u + 3] = f2tf32f(vv.w);
            }
        }
        __syncthreads();

        // S = Q K^T for this warp's 16 rows x 64 keys
        float s[8][4] = {};
        #pragma unroll
        for (int k0 = 0; k0 < 64; k0 += 8) {
            uint32_t a[4];
            a[0] = __float_as_uint(sQ[(m0 + g    ) * ASTR + k0 + tq]);
            a[1] = __float_as_uint(sQ[(m0 + g + 8) * ASTR + k0 + tq]);
            a[2] = __float_as_uint(sQ[(m0 + g    ) * ASTR + k0 + tq + 4]);
            a[3] = __float_as_uint(sQ[(m0 + g + 8) * ASTR + k0 + tq + 4]);
            #pragma unroll
            for (int j = 0; j < 8; j++) {
                uint32_t bfr[2];
                bfr[0] = __float_as_uint(sK[(8*j + g) * ASTR + k0 + tq]);
                bfr[1] = __float_as_uint(sK[(8*j + g) * ASTR + k0 + tq + 4]);
                mma_tf32(s[j], a, bfr);
            }
        }

        // online softmax, fully in registers (rows g and g+8)
        float mx0 = -1e30f, mx1 = -1e30f;
        #pragma unroll
        for (int j = 0; j < 8; j++) {
            mx0 = fmaxf(mx0, fmaxf(s[j][0], s[j][1]));
            mx1 = fmaxf(mx1, fmaxf(s[j][2], s[j][3]));
        }
        mx0 = fmaxf(mx0, __shfl_xor_sync(0xffffffffu, mx0, 1));
        mx0 = fmaxf(mx0, __shfl_xor_sync(0xffffffffu, mx0, 2));
        mx1 = fmaxf(mx1, __shfl_xor_sync(0xffffffffu, mx1, 1));
        mx1 = fmaxf(mx1, __shfl_xor_sync(0xffffffffu, mx1, 2));
        float mn0 = fmaxf(m0run, mx0), mn1 = fmaxf(m1run, mx1);
        float al0 = __expf(m0run - mn0), al1 = __expf(m1run - mn1);
        float ls0 = 0.f, ls1 = 0.f;
        #pragma unroll
        for (int j = 0; j < 8; j++) {
            s[j][0] = __expf(s[j][0] - mn0); ls0 += s[j][0];
            s[j][1] = __expf(s[j][1] - mn0); ls0 += s[j][1];
            s[j][2] = __expf(s[j][2] - mn1); ls1 += s[j][2];
            s[j][3] = __expf(s[j][3] - mn1); ls1 += s[j][3];
        }
        ls0 += __shfl_xor_sync(0xffffffffu, ls0, 1);
        ls0 += __shfl_xor_sync(0xffffffffu, ls0, 2);
        ls1 += __shfl_xor_sync(0xffffffffu, ls1, 1);
        ls1 += __shfl_xor_sync(0xffffffffu, ls1, 2);
        l0run = l0run * al0 + ls0;  m0run = mn0;
        l1run = l1run * al1 + ls1;  m1run = mn1;
        #pragma unroll
        for (int j = 0; j < 8; j++) {
            o[j][0] *= al0; o[j][1] *= al0;
            o[j][2] *= al1; o[j][3] *= al1;
        }

        // P -> per-warp smem region (C-layout store, A-layout reload)
        #pragma unroll
        for (int j = 0; j < 8; j++) {
            sP[(m0 + g    ) * ASTR + 8*j + 2*tq    ] = f2tf32f(s[j][0]);
            sP[(m0 + g    ) * ASTR + 8*j + 2*tq + 1] = f2tf32f(s[j][1]);
            sP[(m0 + g + 8) * ASTR + 8*j + 2*tq    ] = f2tf32f(s[j][2]);
            sP[(m0 + g + 8) * ASTR + 8*j + 2*tq + 1] = f2tf32f(s[j][3]);
        }
        __syncwarp();

        // O += P V
        #pragma unroll
        for (int k0 = 0; k0 < 64; k0 += 8) {
            uint32_t a[4];
            a[0] = __float_as_uint(sP[(m0 + g    ) * ASTR + k0 + tq]);
            a[1] = __float_as_uint(sP[(m0 + g + 8) * ASTR + k0 + tq]);
            a[2] = __float_as_uint(sP[(m0 + g    ) * ASTR + k0 + tq + 4]);
            a[3] = __float_as_uint(sP[(m0 + g + 8) * ASTR + k0 + tq + 4]);
            #pragma unroll
            for (int j = 0; j < 8; j++) {
                uint32_t bfr[2];
                bfr[0] = __float_as_uint(sV[(k0 + tq    ) * ASTR + 8*j + g]);
                bfr[1] = __float_as_uint(sV[(k0 + tq + 4) * ASTR + 8*j + g]);
                mma_tf32(o[j], a, bfr);
            }
        }
        __syncwarp();   // P reads done before next iteration overwrites
    }

    // epilogue
    float inv0 = 1.f / l0run, inv1 = 1.f / l1run;
    int row0 = b * SEQ + qt * 64 + m0 + g;
    #pragma unroll
    for (int j = 0; j < 8; j++) {
        int col = h * DH + 8*j + 2*tq;
        *(float2*)(O + (size_t)row0 * DIM + col) =
            make_float2(o[j][0] * inv0, o[j][1] * inv0);
        *(float2*)(O + (size_t)(row0 + 8) * DIM + col) =
            make_float2(o[j][2] * inv1, o[j][3] * inv1);
    }
}

// ---------------- launch ----------------
extern "C" void kernel_launch(void* const* d_in, const int* in_sizes, int n_in,
                              void* d_out, int out_size) {
    const float* x  = (const float*)d_in[0];
    const float* qw = (const float*)d_in[1];
    const float* kw = (const float*)d_in[2];
    const float* vw = (const float*)d_in[3];
    const float* qb = (const float*)d_in[4];
    const float* kb = (const float*)d_in[5];
    const float* vb = (const float*)d_in[6];
    const float* pw = (const float*)d_in[7];
    const float* pb = (const float*)d_in[8];
    float* out = (float*)d_out;

    float *xn, *q, *k, *v, *att;
    cudaGetSymbolAddress((void**)&xn,  g_xn);
    cudaGetSymbolAddress((void**)&q,   g_q);
    cudaGetSymbolAddress((void**)&k,   g_k);
    cudaGetSymbolAddress((void**)&v,   g_v);
    cudaGetSymbolAddress((void**)&att, g_att);

    cudaFuncSetAttribute(attn_tc,
                         cudaFuncAttributeMaxDynamicSharedMemorySize, SMEM_ATTN);

    ln_kernel<<<ROWS, 256>>>(x, xn);

    dim3 ggrid(DIM / 64, ROWS / 128);   // (12, 32)
    gemm_tc<<<ggrid, 256>>>(xn, qw, qb, nullptr, q);
    gemm_tc<<<ggrid, 256>>>(xn, kw, kb, nullptr, k);
    gemm_tc<<<ggrid, 256>>>(xn, vw, vb, nullptr, v);

    attn_tc<<<dim3(SEQ / 64, NH, BATCH), 128, SMEM_ATTN>>>(q, k, v, att);

    gemm_tc<<<ggrid, 256>>>(att, pw, pb, x, out);   // proj + bias + residual
}

// round 3
// speedup vs baseline: 7.1793x; 2.3037x over previous
#include <cuda_runtime.h>
#include <cuda_bf16.h>
#include <cstdint>

#define DIM 768
#define NH 12
#define DH 64
#define BATCH 4
#define SEQ 1024
#define ROWS (BATCH*SEQ)            // 4096
#define SCALE_ATT 0.125f

// ---------------- scratch (bf16 intermediates) ----------------
__device__ __nv_bfloat16 g_xn [ROWS*DIM];
__device__ __nv_bfloat16 g_q  [ROWS*DIM];
__device__ __nv_bfloat16 g_k  [ROWS*DIM];
__device__ __nv_bfloat16 g_v  [ROWS*DIM];
__device__ __nv_bfloat16 g_att[ROWS*DIM];

// ---------------- helpers ----------------
__device__ __forceinline__ uint32_t saddr(const void* p) {
    return (uint32_t)__cvta_generic_to_shared(p);
}
__device__ __forceinline__ void ldsm4(uint32_t* r, uint32_t a) {
    asm volatile("ldmatrix.sync.aligned.m8n8.x4.shared.b16 {%0,%1,%2,%3}, [%4];"
                 : "=r"(r[0]), "=r"(r[1]), "=r"(r[2]), "=r"(r[3]) : "r"(a));
}
__device__ __forceinline__ void ldsm4t(uint32_t* r, uint32_t a) {
    asm volatile("ldmatrix.sync.aligned.m8n8.x4.trans.shared.b16 {%0,%1,%2,%3}, [%4];"
                 : "=r"(r[0]), "=r"(r[1]), "=r"(r[2]), "=r"(r[3]) : "r"(a));
}
__device__ __forceinline__ void mma16816(float* d, const uint32_t* a, const uint32_t* b) {
    asm volatile("mma.sync.aligned.m16n8k16.row.col.f32.bf16.bf16.f32 "
        "{%0,%1,%2,%3}, {%4,%5,%6,%7}, {%8,%9}, {%0,%1,%2,%3};\n"
        : "+f"(d[0]), "+f"(d[1]), "+f"(d[2]), "+f"(d[3])
        : "r"(a[0]), "r"(a[1]), "r"(a[2]), "r"(a[3]), "r"(b[0]), "r"(b[1]));
}
__device__ __forceinline__ uint32_t packbf(float lo, float hi) {
    __nv_bfloat162 h = __floats2bfloat162_rn(lo, hi);   // x=lo (low half), y=hi
    return *reinterpret_cast<uint32_t*>(&h);
}

// ---------------- LayerNorm (ddof=1), 384 threads, bf16 out ----------------
__global__ void __launch_bounds__(384) ln_kernel(const float* __restrict__ x,
                                                 __nv_bfloat16* __restrict__ xn) {
    int row = blockIdx.x, t = threadIdx.x;
    float2 v = *(const float2*)(x + (size_t)row * DIM + 2 * t);
    float s  = v.x + v.y;
    float sq = v.x * v.x + v.y * v.y;
    #pragma unroll
    for (int o = 16; o; o >>= 1) {
        s  += __shfl_xor_sync(0xffffffffu, s,  o);
        sq += __shfl_xor_sync(0xffffffffu, sq, o);
    }
    __shared__ float rs[12], rq[12];
    int w = t >> 5, l = t & 31;
    if (l == 0) { rs[w] = s; rq[w] = sq; }
    __syncthreads();
    if (w == 0) {
        s  = (l < 12) ? rs[l] : 0.f;
        sq = (l < 12) ? rq[l] : 0.f;
        #pragma unroll
        for (int o = 16; o; o >>= 1) {
            s  += __shfl_xor_sync(0xffffffffu, s,  o);
            sq += __shfl_xor_sync(0xffffffffu, sq, o);
        }
        if (l == 0) { rs[0] = s; rq[0] = sq; }
    }
    __syncthreads();
    s = rs[0]; sq = rq[0];
    float mean = s * (1.f / DIM);
    float var  = (sq - (float)DIM * mean * mean) * (1.f / (DIM - 1));
    float inv  = rsqrtf(var);
    ((uint32_t*)xn)[(size_t)row * (DIM / 2) + t] =
        packbf((v.x - mean) * inv, (v.y - mean) * inv);
}

// ---------------- fused QKV bf16 tensor GEMM --------------------------------
// C[M,N] = A[M,K] @ W[N,K]^T + bias.  BM=128 BN=64 BK=32, 256 thr, 8 warps 4x2.
// grid.x = 36: sel = x/12 picks q/k/v, nb = x%12 picks the 64-col block.
__global__ void __launch_bounds__(256) gemm_qkv(
        const __nv_bfloat16* __restrict__ A,
        const float* __restrict__ qw, const float* __restrict__ kw,
        const float* __restrict__ vw,
        const float* __restrict__ qb, const float* __restrict__ kb,
        const float* __restrict__ vb,
        __nv_bfloat16* __restrict__ qo, __nv_bfloat16* __restrict__ ko,
        __nv_bfloat16* __restrict__ vo) {
    __shared__ __nv_bfloat16 As[128][40];   // 80B rows: LDSM phases conflict-free
    __shared__ __nv_bfloat16 Bs[64][40];
    int nb = blockIdx.x % 12, sel = blockIdx.x / 12;
    const float* W    = sel == 0 ? qw : sel == 1 ? kw : vw;
    const float* bias = sel == 0 ? qb : sel == 1 ? kb : vb;
    __nv_bfloat16* C  = sel == 0 ? qo : sel == 1 ? ko : vo;
    int bm0 = blockIdx.y * 128, bn0 = nb * 64;
    int tid = threadIdx.x, lane = tid & 31, wid = tid >> 5;
    int g = lane >> 2, tq = lane & 3;
    int wm = (wid >> 1) * 32, wn = (wid & 1) * 32;
    int lrA = tid >> 1, lkA = (tid & 1) * 16;
    int lrB = tid >> 2, lkB = (tid & 3) * 8;
    const __nv_bfloat16* Ap = A + (size_t)(bm0 + lrA) * DIM + lkA;
    const float*         Wp = W + (size_t)(bn0 + lrB) * DIM + lkB;

    uint32_t aA = saddr(&As[wm + (lane & 15)][(lane >> 4) * 8]);
    uint32_t aB = saddr(&Bs[wn + (lane & 7) + ((lane >> 4) & 1) * 8]
                           [((lane >> 3) & 1) * 8]);

    float acc[2][4][4] = {};
    for (int kt = 0; kt < DIM; kt += 32) {
        uint4  av0 = *(const uint4*)(Ap + kt);
        uint4  av1 = *(const uint4*)(Ap + kt + 8);
        float4 w0  = *(const float4*)(Wp + kt);
        float4 w1  = *(const float4*)(Wp + kt + 4);
        __syncthreads();
        *(uint4*)&As[lrA][lkA]     = av0;
        *(uint4*)&As[lrA][lkA + 8] = av1;
        uint4 bw;
        bw.x = packbf(w0.x, w0.y); bw.y = packbf(w0.z, w0.w);
        bw.z = packbf(w1.x, w1.y); bw.w = packbf(w1.z, w1.w);
        *(uint4*)&Bs[lrB][lkB] = bw;
        __syncthreads();
        #pragma unroll
        for (int ks = 0; ks < 2; ks++) {
            uint32_t a0[4], a1[4], b0[4], b1[4];
            ldsm4(a0, aA + ks * 32);
            ldsm4(a1, aA + ks * 32 + 16 * 80);
            ldsm4(b0, aB + ks * 32);
            ldsm4(b1, aB + ks * 32 + 16 * 80);
            mma16816(acc[0][0], a0, b0);
            mma16816(acc[0][1], a0, b0 + 2);
            mma16816(acc[0][2], a0, b1);
            mma16816(acc[0][3], a0, b1 + 2);
            mma16816(acc[1][0], a1, b0);
            mma16816(acc[1][1], a1, b0 + 2);
            mma16816(acc[1][2], a1, b1);
            mma16816(acc[1][3], a1, b1 + 2);
        }
    }
    #pragma unroll
    for (int i = 0; i < 2; i++) {
        int row = bm0 + wm + 16 * i + g;
        #pragma unroll
        for (int j = 0; j < 4; j++) {
            int col = bn0 + wn + 8 * j + 2 * tq;
            float bx = bias[col], by = bias[col + 1];
            *(uint32_t*)(C + (size_t)row * DIM + col) =
                packbf(acc[i][j][0] + bx, acc[i][j][1] + by);
            *(uint32_t*)(C + (size_t)(row + 8) * DIM + col) =
                packbf(acc[i][j][2] + bx, acc[i][j][3] + by);
        }
    }
}

// ---------------- proj bf16 GEMM, fp32 out + bias + residual ----------------
__global__ void __launch_bounds__(256) gemm_proj(
        const __nv_bfloat16* __restrict__ A, const float* __restrict__ W,
        const float* __restrict__ bias, const float* __restrict__ res,
        float* __restrict__ C) {
    __shared__ __nv_bfloat16 As[128][40];
    __shared__ __nv_bfloat16 Bs[64][40];
    int bm0 = blockIdx.y * 128, bn0 = blockIdx.x * 64;
    int tid = threadIdx.x, lane = tid & 31, wid = tid >> 5;
    int g = lane >> 2, tq = lane & 3;
    int wm = (wid >> 1) * 32, wn = (wid & 1) * 32;
    int lrA = tid >> 1, lkA = (tid & 1) * 16;
    int lrB = tid >> 2, lkB = (tid & 3) * 8;
    const __nv_bfloat16* Ap = A + (size_t)(bm0 + lrA) * DIM + lkA;
    const float*         Wp = W + (size_t)(bn0 + lrB) * DIM + lkB;

    uint32_t aA = saddr(&As[wm + (lane & 15)][(lane >> 4) * 8]);
    uint32_t aB = saddr(&Bs[wn + (lane & 7) + ((lane >> 4) & 1) * 8]
                           [((lane >> 3) & 1) * 8]);

    float acc[2][4][4] = {};
    for (int kt = 0; kt < DIM; kt += 32) {
        uint4  av0 = *(const uint4*)(Ap + kt);
        uint4  av1 = *(const uint4*)(Ap + kt + 8);
        float4 w0  = *(const float4*)(Wp + kt);
        float4 w1  = *(const float4*)(Wp + kt + 4);
        __syncthreads();
        *(uint4*)&As[lrA][lkA]     = av0;
        *(uint4*)&As[lrA][lkA + 8] = av1;
        uint4 bw;
        bw.x = packbf(w0.x, w0.y); bw.y = packbf(w0.z, w0.w);
        bw.z = packbf(w1.x, w1.y); bw.w = packbf(w1.z, w1.w);
        *(uint4*)&Bs[lrB][lkB] = bw;
        __syncthreads();
        #pragma unroll
        for (int ks = 0; ks < 2; ks++) {
            uint32_t a0[4], a1[4], b0[4], b1[4];
            ldsm4(a0, aA + ks * 32);
            ldsm4(a1, aA + ks * 32 + 16 * 80);
            ldsm4(b0, aB + ks * 32);
            ldsm4(b1, aB + ks * 32 + 16 * 80);
            mma16816(acc[0][0], a0, b0);
            mma16816(acc[0][1], a0, b0 + 2);
            mma16816(acc[0][2], a0, b1);
            mma16816(acc[0][3], a0, b1 + 2);
            mma16816(acc[1][0], a1, b0);
            mma16816(acc[1][1], a1, b0 + 2);
            mma16816(acc[1][2], a1, b1);
            mma16816(acc[1][3], a1, b1 + 2);
        }
    }
    #pragma unroll
    for (int i = 0; i < 2; i++) {
        int row = bm0 + wm + 16 * i + g;
        #pragma unroll
        for (int j = 0; j < 4; j++) {
            int col = bn0 + wn + 8 * j + 2 * tq;
            float bx = bias[col], by = bias[col + 1];
            size_t o0 = (size_t)row * DIM + col;
            size_t o1 = (size_t)(row + 8) * DIM + col;
            float2 e0 = *(const float2*)(res + o0);
            float2 e1 = *(const float2*)(res + o1);
            *(float2*)(C + o0) = make_float2(acc[i][j][0] + bx + e0.x,
                                             acc[i][j][1] + by + e0.y);
            *(float2*)(C + o1) = make_float2(acc[i][j][2] + bx + e1.x,
                                             acc[i][j][3] + by + e1.y);
        }
    }
}

// ---------------- bf16 tensor flash attention -------------------------------
// grid (SEQ/64, NH, BATCH), 128 thr (4 warps), warp owns 16 Q rows.
__global__ void __launch_bounds__(128) attn_tc(const __nv_bfloat16* __restrict__ Q,
                                               const __nv_bfloat16* __restrict__ K,
                                               const __nv_bfloat16* __restrict__ V,
                                               __nv_bfloat16* __restrict__ O) {
    __shared__ __nv_bfloat16 sQ[64][72];   // 144B rows: LDSM conflict-free
    __shared__ __nv_bfloat16 sK[64][72];
    __shared__ __nv_bfloat16 sV[64][72];
    __shared__ __nv_bfloat16 sP[64][72];

    int qt = blockIdx.x, h = blockIdx.y, b = blockIdx.z;
    int tid = threadIdx.x, lane = tid & 31, wid = tid >> 5;
    int g = lane >> 2, tq = lane & 3;
    int m0 = wid * 16;
    int lr = tid >> 1, half = tid & 1;      // loader: row, 32-col half

    // load Q tile (bf16 raw copy; scale applied to S later)
    {
        const uint4* qp = (const uint4*)(Q + (size_t)(b * SEQ + qt * 64 + lr) * DIM
                                           + h * DH + half * 32);
        uint4* dq = (uint4*)&sQ[lr][half * 32];
        #pragma unroll
        for (int u = 0; u < 4; u++) dq[u] = qp[u];
    }

    uint32_t aQ = saddr(&sQ[m0 + (lane & 15)][(lane >> 4) * 8]);
    uint32_t aP = saddr(&sP[m0 + (lane & 15)][(lane >> 4) * 8]);
    uint32_t aK = saddr(&sK[(lane & 7) + ((lane >> 4) & 1) * 8]
                           [((lane >> 3) & 1) * 8]);
    uint32_t aV = saddr(&sV[(lane & 7) + ((lane >> 3) & 1) * 8]
                           [(lane >> 4) * 8]);   // trans addressing

    float m0r = -1e30f, m1r = -1e30f, l0r = 0.f, l1r = 0.f;
    float o[8][4] = {};

    for (int kt = 0; kt < SEQ / 64; kt++) {
        __syncthreads();
        {
            const uint4* kp = (const uint4*)(K + (size_t)(b * SEQ + kt * 64 + lr) * DIM
                                               + h * DH + half * 32);
            const uint4* vp = (const uint4*)(V + (size_t)(b * SEQ + kt * 64 + lr) * DIM
                                               + h * DH + half * 32);
            uint4* dk = (uint4*)&sK[lr][half * 32];
            uint4* dv = (uint4*)&sV[lr][half * 32];
            #pragma unroll
            for (int u = 0; u < 4; u++) { dk[u] = kp[u]; dv[u] = vp[u]; }
        }
        __syncthreads();

        // S = Q K^T (warp's 16 rows x 64 keys)
        float s[8][4] = {};
        #pragma unroll
        for (int ks = 0; ks < 4; ks++) {
            uint32_t a[4];
            ldsm4(a, aQ + ks * 32);
            #pragma unroll
            for (int j2 = 0; j2 < 4; j2++) {
                uint32_t bb[4];
                ldsm4(bb, aK + j2 * (16 * 144) + ks * 32);
                mma16816(s[2 * j2],     a, bb);
                mma16816(s[2 * j2 + 1], a, bb + 2);
            }
        }
        #pragma unroll
        for (int j = 0; j < 8; j++)
            #pragma unroll
            for (int c = 0; c < 4; c++) s[j][c] *= SCALE_ATT;

        // online softmax in registers (rows g and g+8)
        float mx0 = -1e30f, mx1 = -1e30f;
        #pragma unroll
        for (int j = 0; j < 8; j++) {
            mx0 = fmaxf(mx0, fmaxf(s[j][0], s[j][1]));
            mx1 = fmaxf(mx1, fmaxf(s[j][2], s[j][3]));
        }
        mx0 = fmaxf(mx0, __shfl_xor_sync(0xffffffffu, mx0, 1));
        mx0 = fmaxf(mx0, __shfl_xor_sync(0xffffffffu, mx0, 2));
        mx1 = fmaxf(mx1, __shfl_xor_sync(0xffffffffu, mx1, 1));
        mx1 = fmaxf(mx1, __shfl_xor_sync(0xffffffffu, mx1, 2));
        float mn0 = fmaxf(m0r, mx0), mn1 = fmaxf(m1r, mx1);
        float al0 = __expf(m0r - mn0), al1 = __expf(m1r - mn1);
        float ls0 = 0.f, ls1 = 0.f;
        #pragma unroll
        for (int j = 0; j < 8; j++) {
            s[j][0] = __expf(s[j][0] - mn0); ls0 += s[j][0];
            s[j][1] = __expf(s[j][1] - mn0); ls0 += s[j][1];
            s[j][2] = __expf(s[j][2] - mn1); ls1 += s[j][2];
            s[j][3] = __expf(s[j][3] - mn1); ls1 += s[j][3];
        }
        ls0 += __shfl_xor_sync(0xffffffffu, ls0, 1);
        ls0 += __shfl_xor_sync(0xffffffffu, ls0, 2);
        ls1 += __shfl_xor_sync(0xffffffffu, ls1, 1);
        ls1 += __shfl_xor_sync(0xffffffffu, ls1, 2);
        l0r = l0r * al0 + ls0;  m0r = mn0;
        l1r = l1r * al1 + ls1;  m1r = mn1;
        #pragma unroll
        for (int j = 0; j < 8; j++) {
            o[j][0] *= al0; o[j][1] *= al0;
            o[j][2] *= al1; o[j][3] *= al1;
        }

        // P -> per-warp smem (bf16 pairs)
        {
            uint32_t* p0 = (uint32_t*)&sP[m0 + g][0];
            uint32_t* p1 = (uint32_t*)&sP[m0 + g + 8][0];
            #pragma unroll
            for (int j = 0; j < 8; j++) {
                p0[4 * j + tq] = packbf(s[j][0], s[j][1]);
                p1[4 * j + tq] = packbf(s[j][2], s[j][3]);
            }
        }
        __syncwarp();

        // O += P V  (V via ldmatrix.trans)
        #pragma unroll
        for (int ks = 0; ks < 4; ks++) {
            uint32_t a[4];
            ldsm4(a, aP + ks * 32);
            #pragma unroll
            for (int j2 = 0; j2 < 4; j2++) {
                uint32_t bb[4];
                ldsm4t(bb, aV + ks * (16 * 144) + j2 * 32);
                mma16816(o[2 * j2],     a, bb);
                mma16816(o[2 * j2 + 1], a, bb + 2);
            }
        }
        __syncwarp();
    }

    float inv0 = 1.f / l0r, inv1 = 1.f / l1r;
    int row0 = b * SEQ + qt * 64 + m0 + g;
    #pragma unroll
    for (int j = 0; j < 8; j++) {
        int col = h * DH + 8 * j + 2 * tq;
        *(uint32_t*)(O + (size_t)row0 * DIM + col) =
            packbf(o[j][0] * inv0, o[j][1] * inv0);
        *(uint32_t*)(O + (size_t)(row0 + 8) * DIM + col) =
            packbf(o[j][2] * inv1, o[j][3] * inv1);
    }
}

// ---------------- launch ----------------
extern "C" void kernel_launch(void* const* d_in, const int* in_sizes, int n_in,
                              void* d_out, int out_size) {
    const float* x  = (const float*)d_in[0];
    const float* qw = (const float*)d_in[1];
    const float* kw = (const float*)d_in[2];
    const float* vw = (const float*)d_in[3];
    const float* qb = (const float*)d_in[4];
    const float* kb = (const float*)d_in[5];
    const float* vb = (const float*)d_in[6];
    const float* pw = (const float*)d_in[7];
    const float* pb = (const float*)d_in[8];
    float* out = (float*)d_out;

    __nv_bfloat16 *xn, *q, *k, *v, *att;
    cudaGetSymbolAddress((void**)&xn,  g_xn);
    cudaGetSymbolAddress((void**)&q,   g_q);
    cudaGetSymbolAddress((void**)&k,   g_k);
    cudaGetSymbolAddress((void**)&v,   g_v);
    cudaGetSymbolAddress((void**)&att, g_att);

    ln_kernel<<<ROWS, 384>>>(x, xn);

    gemm_qkv<<<dim3(36, 32), 256>>>(xn, qw, kw, vw, qb, kb, vb, q, k, v);

    attn_tc<<<dim3(SEQ / 64, NH, BATCH), 128>>>(q, k, v, att);

    gemm_proj<<<dim3(12, 32), 256>>>(att, pw, pb, x, out);
}

// round 4
// speedup vs baseline: 8.1663x; 1.1375x over previous
#include <cuda_runtime.h>
#include <cuda_bf16.h>
#include <cstdint>

#define DIM 768
#define NH 12
#define DH 64
#define BATCH 4
#define SEQ 1024
#define ROWS (BATCH*SEQ)            // 4096
#define SCALE_ATT 0.125f

// ---------------- scratch ----------------
__device__ __nv_bfloat16 g_xn [ROWS*DIM];
__device__ __nv_bfloat16 g_q  [ROWS*DIM];
__device__ __nv_bfloat16 g_k  [ROWS*DIM];
__device__ __nv_bfloat16 g_v  [ROWS*DIM];
__device__ __nv_bfloat16 g_att[ROWS*DIM];
__device__ __nv_bfloat16 g_wb [4 * DIM * DIM];   // bf16 weights: q,k,v,proj

// ---------------- helpers ----------------
__device__ __forceinline__ uint32_t saddr(const void* p) {
    return (uint32_t)__cvta_generic_to_shared(p);
}
__device__ __forceinline__ void cp16(void* s, const void* g) {
    asm volatile("cp.async.cg.shared.global [%0], [%1], 16;\n"
                 :: "r"(saddr(s)), "l"(g));
}
__device__ __forceinline__ void cp_commit() {
    asm volatile("cp.async.commit_group;\n");
}
__device__ __forceinline__ void ldsm4(uint32_t* r, uint32_t a) {
    asm volatile("ldmatrix.sync.aligned.m8n8.x4.shared.b16 {%0,%1,%2,%3}, [%4];"
                 : "=r"(r[0]), "=r"(r[1]), "=r"(r[2]), "=r"(r[3]) : "r"(a));
}
__device__ __forceinline__ void ldsm4t(uint32_t* r, uint32_t a) {
    asm volatile("ldmatrix.sync.aligned.m8n8.x4.trans.shared.b16 {%0,%1,%2,%3}, [%4];"
                 : "=r"(r[0]), "=r"(r[1]), "=r"(r[2]), "=r"(r[3]) : "r"(a));
}
__device__ __forceinline__ void mma16816(float* d, const uint32_t* a, const uint32_t* b) {
    asm volatile("mma.sync.aligned.m16n8k16.row.col.f32.bf16.bf16.f32 "
        "{%0,%1,%2,%3}, {%4,%5,%6,%7}, {%8,%9}, {%0,%1,%2,%3};\n"
        : "+f"(d[0]), "+f"(d[1]), "+f"(d[2]), "+f"(d[3])
        : "r"(a[0]), "r"(a[1]), "r"(a[2]), "r"(a[3]), "r"(b[0]), "r"(b[1]));
}
__device__ __forceinline__ uint32_t packbf(float lo, float hi) {
    __nv_bfloat162 h = __floats2bfloat162_rn(lo, hi);
    return *reinterpret_cast<uint32_t*>(&h);
}

// ---------------- weight fp32 -> bf16 ----------------
__global__ void __launch_bounds__(256) cvt_w(const float* __restrict__ s0,
                                             const float* __restrict__ s1,
                                             const float* __restrict__ s2,
                                             const float* __restrict__ s3,
                                             __nv_bfloat16* __restrict__ d) {
    int m = blockIdx.y;
    const float* s = m == 0 ? s0 : m == 1 ? s1 : m == 2 ? s2 : s3;
    __nv_bfloat16* dp = d + (size_t)m * DIM * DIM;
    int i = (blockIdx.x * 256 + threadIdx.x) * 4;
    float4 v = *(const float4*)(s + i);
    uint2 o;
    o.x = packbf(v.x, v.y);
    o.y = packbf(v.z, v.w);
    *(uint2*)(dp + i) = o;
}

// ---------------- LayerNorm (ddof=1) ----------------
__global__ void __launch_bounds__(384) ln_kernel(const float* __restrict__ x,
                                                 __nv_bfloat16* __restrict__ xn) {
    int row = blockIdx.x, t = threadIdx.x;
    float2 v = *(const float2*)(x + (size_t)row * DIM + 2 * t);
    float s  = v.x + v.y;
    float sq = v.x * v.x + v.y * v.y;
    #pragma unroll
    for (int o = 16; o; o >>= 1) {
        s  += __shfl_xor_sync(0xffffffffu, s,  o);
        sq += __shfl_xor_sync(0xffffffffu, sq, o);
    }
    __shared__ float rs[12], rq[12];
    int w = t >> 5, l = t & 31;
    if (l == 0) { rs[w] = s; rq[w] = sq; }
    __syncthreads();
    if (w == 0) {
        s  = (l < 12) ? rs[l] : 0.f;
        sq = (l < 12) ? rq[l] : 0.f;
        #pragma unroll
        for (int o = 16; o; o >>= 1) {
            s  += __shfl_xor_sync(0xffffffffu, s,  o);
            sq += __shfl_xor_sync(0xffffffffu, sq, o);
        }
        if (l == 0) { rs[0] = s; rq[0] = sq; }
    }
    __syncthreads();
    s = rs[0]; sq = rq[0];
    float mean = s * (1.f / DIM);
    float var  = (sq - (float)DIM * mean * mean) * (1.f / (DIM - 1));
    float inv  = rsqrtf(var);
    ((uint32_t*)xn)[(size_t)row * (DIM / 2) + t] =
        packbf((v.x - mean) * inv, (v.y - mean) * inv);
}

// ---------------- bf16 pipelined GEMM-NT ------------------------------------
// C[M,N] = A[M,K] @ W[N,K]^T + bias (+res).  BM=128 BN=128 BK=32, 256 thr.
// 8 warps 2(m)x4(n); warp tile 64x32. 2-stage cp.async pipeline.
// mode 0: bf16 out (+bias), sel = blockIdx.x/6 picks q/k/v.
// mode 1: fp32 out + bias + residual.
#define NKT (DIM / 32)   // 24
__global__ void __launch_bounds__(256) gemm_bf(
        const __nv_bfloat16* __restrict__ A,
        const __nv_bfloat16* __restrict__ Wall,
        const float* __restrict__ b0, const float* __restrict__ b1,
        const float* __restrict__ b2,
        __nv_bfloat16* __restrict__ c0, __nv_bfloat16* __restrict__ c1,
        __nv_bfloat16* __restrict__ c2,
        const float* __restrict__ res, float* __restrict__ outF,
        int mode) {
    __shared__ __nv_bfloat16 As[2][128][40];   // 80B rows, LDSM conflict-free
    __shared__ __nv_bfloat16 Bs[2][128][40];

    int nb, sel;
    if (mode == 0) { sel = blockIdx.x / 6; nb = blockIdx.x % 6; }
    else           { sel = 3;              nb = blockIdx.x; }
    const __nv_bfloat16* W = Wall + (size_t)sel * DIM * DIM;
    const float* bias = mode == 0 ? (sel == 0 ? b0 : sel == 1 ? b1 : b2) : b0;
    __nv_bfloat16* Cb = sel == 0 ? c0 : sel == 1 ? c1 : c2;

    int bm0 = blockIdx.y * 128, bn0 = nb * 128;
    int tid = threadIdx.x, lane = tid & 31, wid = tid >> 5;
    int g = lane >> 2, tq = lane & 3;
    int wm = (wid >> 2) * 64, wn = (wid & 3) * 32;

    int lr = tid >> 1, lk = (tid & 1) * 16;   // loader: row, elem-offset
    const __nv_bfloat16* Ag = A + (size_t)(bm0 + lr) * DIM + lk;
    const __nv_bfloat16* Wg = W + (size_t)(bn0 + lr) * DIM + lk;

    float acc[4][4][4] = {};

    // prefetch stage 0
    {
        cp16(&As[0][lr][lk],     Ag);
        cp16(&As[0][lr][lk + 8], Ag + 8);
        cp16(&Bs[0][lr][lk],     Wg);
        cp16(&Bs[0][lr][lk + 8], Wg + 8);
        cp_commit();
    }

    for (int kt = 0; kt < NKT; kt++) {
        int s = kt & 1;
        if (kt + 1 < NKT) {
            const __nv_bfloat16* ag = Ag + (kt + 1) * 32;
            const __nv_bfloat16* wg = Wg + (kt + 1) * 32;
            cp16(&As[s ^ 1][lr][lk],     ag);
            cp16(&As[s ^ 1][lr][lk + 8], ag + 8);
            cp16(&Bs[s ^ 1][lr][lk],     wg);
            cp16(&Bs[s ^ 1][lr][lk + 8], wg + 8);
            cp_commit();
            asm volatile("cp.async.wait_group 1;\n");
        } else {
            asm volatile("cp.async.wait_group 0;\n");
        }
        __syncthreads();

        uint32_t aA = saddr(&As[s][wm + (lane & 15)][(lane >> 4) * 8]);
        uint32_t aB = saddr(&Bs[s][wn + (lane & 7) + ((lane >> 4) & 1) * 8]
                               [((lane >> 3) & 1) * 8]);
        #pragma unroll
        for (int ks = 0; ks < 2; ks++) {
            uint32_t a[4][4], b[2][4];
            #pragma unroll
            for (int mt = 0; mt < 4; mt++)
                ldsm4(a[mt], aA + mt * (16 * 80) + ks * 32);
            #pragma unroll
            for (int nt = 0; nt < 2; nt++)
                ldsm4(b[nt], aB + nt * (16 * 80) + ks * 32);
            #pragma unroll
            for (int mt = 0; mt < 4; mt++) {
                #pragma unroll
                for (int nt = 0; nt < 2; nt++) {
                    mma16816(acc[mt][2 * nt],     a[mt], b[nt]);
                    mma16816(acc[mt][2 * nt + 1], a[mt], b[nt] + 2);
                }
            }
        }
        __syncthreads();
    }

    #pragma unroll
    for (int mt = 0; mt < 4; mt++) {
        int row = bm0 + wm + 16 * mt + g;
        #pragma unroll
        for (int j = 0; j < 4; j++) {
            int col = bn0 + wn + 8 * j + 2 * tq;
            float bx = bias[col], by = bias[col + 1];
            size_t o0 = (size_t)row * DIM + col;
            size_t o1 = (size_t)(row + 8) * DIM + col;
            if (mode == 0) {
                *(uint32_t*)(Cb + o0) = packbf(acc[mt][j][0] + bx,
                                               acc[mt][j][1] + by);
                *(uint32_t*)(Cb + o1) = packbf(acc[mt][j][2] + bx,
                                               acc[mt][j][3] + by);
            } else {
                float2 e0 = *(const float2*)(res + o0);
                float2 e1 = *(const float2*)(res + o1);
                *(float2*)(outF + o0) = make_float2(acc[mt][j][0] + bx + e0.x,
                                                    acc[mt][j][1] + by + e0.y);
                *(float2*)(outF + o1) = make_float2(acc[mt][j][2] + bx + e1.x,
                                                    acc[mt][j][3] + by + e1.y);
            }
        }
    }
}

// ---------------- bf16 flash attention, cp.async double-buffered ------------
// grid (SEQ/64, NH, BATCH), 128 thr (4 warps), warp owns 16 Q rows.
// dyn smem: sQ[64*72] | sK[2][64*72] | sV[2][64*72] | sP[64*72]
#define ATILE 4608              // 64*72 elems
#define SMEM_ATTN (6 * ATILE * 2)
__global__ void __launch_bounds__(128) attn_tc(const __nv_bfloat16* __restrict__ Q,
                                               const __nv_bfloat16* __restrict__ K,
                                               const __nv_bfloat16* __restrict__ V,
                                               __nv_bfloat16* __restrict__ O) {
    extern __shared__ __nv_bfloat16 smb[];
    __nv_bfloat16* sQ = smb;
    __nv_bfloat16* sK = smb + ATILE;
    __nv_bfloat16* sV = smb + 3 * ATILE;
    __nv_bfloat16* sP = smb + 5 * ATILE;

    int qt = blockIdx.x, h = blockIdx.y, b = blockIdx.z;
    int tid = threadIdx.x, lane = tid & 31, wid = tid >> 5;
    int g = lane >> 2, tq = lane & 3;
    int m0 = wid * 16;
    int lr = tid >> 1, lk = (tid & 1) * 32;   // loader: row, 32-elem half

    const __nv_bfloat16* Kg = K + (size_t)(b * SEQ + lr) * DIM + h * DH + lk;
    const __nv_bfloat16* Vg = V + (size_t)(b * SEQ + lr) * DIM + h * DH + lk;

    // Q tile (plain copy; first loop barrier covers it)
    {
        const uint4* qp = (const uint4*)(Q + (size_t)(b * SEQ + qt * 64 + lr) * DIM
                                           + h * DH + lk);
        uint4* dq = (uint4*)&sQ[lr * 72 + lk];
        #pragma unroll
        for (int u = 0; u < 4; u++) dq[u] = qp[u];
    }

    // prefetch K/V tile 0 into stage 0
    {
        #pragma unroll
        for (int c = 0; c < 4; c++) {
            cp16(&sK[lr * 72 + lk + c * 8], Kg + c * 8);
            cp16(&sV[lr * 72 + lk + c * 8], Vg + c * 8);
        }
        cp_commit();
    }

    uint32_t aQ = saddr(&sQ[(m0 + (lane & 15)) * 72 + (lane >> 4) * 8]);
    uint32_t aP = saddr(&sP[(m0 + (lane & 15)) * 72 + (lane >> 4) * 8]);
    uint32_t aK0 = saddr(&sK[((lane & 7) + ((lane >> 4) & 1) * 8) * 72
                             + ((lane >> 3) & 1) * 8]);
    uint32_t aV0 = saddr(&sV[((lane & 7) + ((lane >> 3) & 1) * 8) * 72
                             + (lane >> 4) * 8]);

    float m0r = -1e30f, m1r = -1e30f, l0r = 0.f, l1r = 0.f;
    float o[8][4] = {};

    for (int kt = 0; kt < SEQ / 64; kt++) {
        int s = kt & 1;
        if (kt + 1 < SEQ / 64) {
            int so = (s ^ 1) * ATILE;
            const __nv_bfloat16* kg = Kg + (size_t)(kt + 1) * 64 * DIM;
            const __nv_bfloat16* vg = Vg + (size_t)(kt + 1) * 64 * DIM;
            #pragma unroll
            for (int c = 0; c < 4; c++) {
                cp16(&sK[so + lr * 72 + lk + c * 8], kg + c * 8);
                cp16(&sV[so + lr * 72 + lk + c * 8], vg + c * 8);
            }
            cp_commit();
            asm volatile("cp.async.wait_group 1;\n");
        } else {
            asm volatile("cp.async.wait_group 0;\n");
        }
        __syncthreads();

        uint32_t aK = aK0 + s * (ATILE * 2);
        uint32_t aV = aV0 + s * (ATILE * 2);

        // S = Q K^T
        float sc[8][4] = {};
        #pragma unroll
        for (int ks = 0; ks < 4; ks++) {
            uint32_t a[4];
            ldsm4(a, aQ + ks * 32);
            #pragma unroll
            for (int j2 = 0; j2 < 4; j2++) {
                uint32_t bb[4];
                ldsm4(bb, aK + j2 * (16 * 144) + ks * 32);
                mma16816(sc[2 * j2],     a, bb);
                mma16816(sc[2 * j2 + 1], a, bb + 2);
            }
        }
        #pragma unroll
        for (int j = 0; j < 8; j++)
            #pragma unroll
            for (int c = 0; c < 4; c++) sc[j][c] *= SCALE_ATT;

        // online softmax in registers
        float mx0 = -1e30f, mx1 = -1e30f;
        #pragma unroll
        for (int j = 0; j < 8; j++) {
            mx0 = fmaxf(mx0, fmaxf(sc[j][0], sc[j][1]));
            mx1 = fmaxf(mx1, fmaxf(sc[j][2], sc[j][3]));
        }
        mx0 = fmaxf(mx0, __shfl_xor_sync(0xffffffffu, mx0, 1));
        mx0 = fmaxf(mx0, __shfl_xor_sync(0xffffffffu, mx0, 2));
        mx1 = fmaxf(mx1, __shfl_xor_sync(0xffffffffu, mx1, 1));
        mx1 = fmaxf(mx1, __shfl_xor_sync(0xffffffffu, mx1, 2));
        float mn0 = fmaxf(m0r, mx0), mn1 = fmaxf(m1r, mx1);
        float al0 = __expf(m0r - mn0), al1 = __expf(m1r - mn1);
        float ls0 = 0.f, ls1 = 0.f;
        #pragma unroll
        for (int j = 0; j < 8; j++) {
            sc[j][0] = __expf(sc[j][0] - mn0); ls0 += sc[j][0];
            sc[j][1] = __expf(sc[j][1] - mn0); ls0 += sc[j][1];
            sc[j][2] = __expf(sc[j][2] - mn1); ls1 += sc[j][2];
            sc[j][3] = __expf(sc[j][3] - mn1); ls1 += sc[j][3];
        }
        ls0 += __shfl_xor_sync(0xffffffffu, ls0, 1);
        ls0 += __shfl_xor_sync(0xffffffffu, ls0, 2);
        ls1 += __shfl_xor_sync(0xffffffffu, ls1, 1);
        ls1 += __shfl_xor_sync(0xffffffffu, ls1, 2);
        l0r = l0r * al0 + ls0;  m0r = mn0;
        l1r = l1r * al1 + ls1;  m1r = mn1;
        #pragma unroll
        for (int j = 0; j < 8; j++) {
            o[j][0] *= al0; o[j][1] *= al0;
            o[j][2] *= al1; o[j][3] *= al1;
        }

        // P -> per-warp smem (bf16)
        {
            uint32_t* p0 = (uint32_t*)&sP[(m0 + g) * 72];
            uint32_t* p1 = (uint32_t*)&sP[(m0 + g + 8) * 72];
            #pragma unroll
            for (int j = 0; j < 8; j++) {
                p0[4 * j + tq] = packbf(sc[j][0], sc[j][1]);
                p1[4 * j + tq] = packbf(sc[j][2], sc[j][3]);
            }
        }
        __syncwarp();

        // O += P V  (V via ldmatrix.trans)
        #pragma unroll
        for (int ks = 0; ks < 4; ks++) {
            uint32_t a[4];
            ldsm4(a, aP + ks * 32);
            #pragma unroll
            for (int j2 = 0; j2 < 4; j2++) {
                uint32_t bb[4];
                ldsm4t(bb, aV + ks * (16 * 144) + j2 * 32);
                mma16816(o[2 * j2],     a, bb);
                mma16816(o[2 * j2 + 1], a, bb + 2);
            }
        }
        __syncthreads();
    }

    float inv0 = 1.f / l0r, inv1 = 1.f / l1r;
    int row0 = b * SEQ + qt * 64 + m0 + g;
    #pragma unroll
    for (int j = 0; j < 8; j++) {
        int col = h * DH + 8 * j + 2 * tq;
        *(uint32_t*)(O + (size_t)row0 * DIM + col) =
            packbf(o[j][0] * inv0, o[j][1] * inv0);
        *(uint32_t*)(O + (size_t)(row0 + 8) * DIM + col) =
            packbf(o[j][2] * inv1, o[j][3] * inv1);
    }
}

// ---------------- launch ----------------
extern "C" void kernel_launch(void* const* d_in, const int* in_sizes, int n_in,
                              void* d_out, int out_size) {
    const float* x  = (const float*)d_in[0];
    const float* qw = (const float*)d_in[1];
    const float* kw = (const float*)d_in[2];
    const float* vw = (const float*)d_in[3];
    const float* qb = (const float*)d_in[4];
    const float* kb = (const float*)d_in[5];
    const float* vb = (const float*)d_in[6];
    const float* pw = (const float*)d_in[7];
    const float* pb = (const float*)d_in[8];
    float* out = (float*)d_out;

    __nv_bfloat16 *xn, *q, *k, *v, *att, *wb;
    cudaGetSymbolAddress((void**)&xn,  g_xn);
    cudaGetSymbolAddress((void**)&q,   g_q);
    cudaGetSymbolAddress((void**)&k,   g_k);
    cudaGetSymbolAddress((void**)&v,   g_v);
    cudaGetSymbolAddress((void**)&att, g_att);
    cudaGetSymbolAddress((void**)&wb,  g_wb);

    cudaFuncSetAttribute(attn_tc,
                         cudaFuncAttributeMaxDynamicSharedMemorySize, SMEM_ATTN);

    cvt_w<<<dim3(DIM * DIM / 1024, 4), 256>>>(qw, kw, vw, pw, wb);
    ln_kernel<<<ROWS, 384>>>(x, xn);

    // QKV: 18 x 32 blocks (sel = x/6)
    gemm_bf<<<dim3(18, 32), 256>>>(xn, wb, qb, kb, vb, q, k, v,
                                   nullptr, nullptr, 0);

    attn_tc<<<dim3(SEQ / 64, NH, BATCH), 128, SMEM_ATTN>>>(q, k, v, att);

    // proj: 6 x 32 blocks, fp32 out + bias + residual
    gemm_bf<<<dim3(6, 32), 256>>>(att, wb, pb, nullptr, nullptr,
                                  nullptr, nullptr, nullptr, x, out, 1);
}

// round 6
// speedup vs baseline: 9.1267x; 1.1176x over previous
#include <cuda_runtime.h>
#include <cuda_bf16.h>
#include <cstdint>

#define DIM 768
#define NH 12
#define DH 64
#define BATCH 4
#define SEQ 1024
#define ROWS (BATCH*SEQ)            // 4096
#define SCALE_ATT 0.125f

// ---------------- scratch ----------------
__device__ __nv_bfloat16 g_xn [ROWS*DIM];
__device__ __nv_bfloat16 g_q  [ROWS*DIM];
__device__ __nv_bfloat16 g_k  [ROWS*DIM];
__device__ __nv_bfloat16 g_v  [ROWS*DIM];
__device__ __nv_bfloat16 g_att[ROWS*DIM];
__device__ __nv_bfloat16 g_wb [4 * DIM * DIM];   // bf16 weights: q,k,v,proj

// ---------------- helpers ----------------
__device__ __forceinline__ uint32_t saddr(const void* p) {
    return (uint32_t)__cvta_generic_to_shared(p);
}
__device__ __forceinline__ void cp16(void* s, const void* g) {
    asm volatile("cp.async.cg.shared.global [%0], [%1], 16;\n"
                 :: "r"(saddr(s)), "l"(g));
}
__device__ __forceinline__ void cp_commit() {
    asm volatile("cp.async.commit_group;\n");
}
__device__ __forceinline__ void ldsm4(uint32_t* r, uint32_t a) {
    asm volatile("ldmatrix.sync.aligned.m8n8.x4.shared.b16 {%0,%1,%2,%3}, [%4];"
                 : "=r"(r[0]), "=r"(r[1]), "=r"(r[2]), "=r"(r[3]) : "r"(a));
}
__device__ __forceinline__ void ldsm4t(uint32_t* r, uint32_t a) {
    asm volatile("ldmatrix.sync.aligned.m8n8.x4.trans.shared.b16 {%0,%1,%2,%3}, [%4];"
                 : "=r"(r[0]), "=r"(r[1]), "=r"(r[2]), "=r"(r[3]) : "r"(a));
}
__device__ __forceinline__ void mma16816(float* d, const uint32_t* a, const uint32_t* b) {
    asm volatile("mma.sync.aligned.m16n8k16.row.col.f32.bf16.bf16.f32 "
        "{%0,%1,%2,%3}, {%4,%5,%6,%7}, {%8,%9}, {%0,%1,%2,%3};\n"
        : "+f"(d[0]), "+f"(d[1]), "+f"(d[2]), "+f"(d[3])
        : "r"(a[0]), "r"(a[1]), "r"(a[2]), "r"(a[3]), "r"(b[0]), "r"(b[1]));
}
__device__ __forceinline__ uint32_t packbf(float lo, float hi) {
    __nv_bfloat162 h = __floats2bfloat162_rn(lo, hi);
    return *reinterpret_cast<uint32_t*>(&h);
}

// ---------------- weight fp32 -> bf16 ----------------
__global__ void __launch_bounds__(256) cvt_w(const float* __restrict__ s0,
                                             const float* __restrict__ s1,
                                             const float* __restrict__ s2,
                                             const float* __restrict__ s3,
                                             __nv_bfloat16* __restrict__ d) {
    int m = blockIdx.y;
    const float* s = m == 0 ? s0 : m == 1 ? s1 : m == 2 ? s2 : s3;
    __nv_bfloat16* dp = d + (size_t)m * DIM * DIM;
    int i = (blockIdx.x * 256 + threadIdx.x) * 4;
    float4 v = *(const float4*)(s + i);
    uint2 o;
    o.x = packbf(v.x, v.y);
    o.y = packbf(v.z, v.w);
    *(uint2*)(dp + i) = o;
}

// ---------------- LayerNorm (ddof=1) ----------------
__global__ void __launch_bounds__(384) ln_kernel(const float* __restrict__ x,
                                                 __nv_bfloat16* __restrict__ xn) {
    int row = blockIdx.x, t = threadIdx.x;
    float2 v = *(const float2*)(x + (size_t)row * DIM + 2 * t);
    float s  = v.x + v.y;
    float sq = v.x * v.x + v.y * v.y;
    #pragma unroll
    for (int o = 16; o; o >>= 1) {
        s  += __shfl_xor_sync(0xffffffffu, s,  o);
        sq += __shfl_xor_sync(0xffffffffu, sq, o);
    }
    __shared__ float rs[12], rq[12];
    int w = t >> 5, l = t & 31;
    if (l == 0) { rs[w] = s; rq[w] = sq; }
    __syncthreads();
    if (w == 0) {
        s  = (l < 12) ? rs[l] : 0.f;
        sq = (l < 12) ? rq[l] : 0.f;
        #pragma unroll
        for (int o = 16; o; o >>= 1) {
            s  += __shfl_xor_sync(0xffffffffu, s,  o);
            sq += __shfl_xor_sync(0xffffffffu, sq, o);
        }
        if (l == 0) { rs[0] = s; rq[0] = sq; }
    }
    __syncthreads();
    s = rs[0]; sq = rq[0];
    float mean = s * (1.f / DIM);
    float var  = (sq - (float)DIM * mean * mean) * (1.f / (DIM - 1));
    float inv  = rsqrtf(var);
    ((uint32_t*)xn)[(size_t)row * (DIM / 2) + t] =
        packbf((v.x - mean) * inv, (v.y - mean) * inv);
}

// ---------------- bf16 3-stage pipelined GEMM-NT ----------------------------
// C[M,N] = A[M,K] @ W[N,K]^T + bias (+res).  BM=128 BN=128 BK=32, 256 thr.
// 8 warps 2(m)x4(n); warp tile 64x32. 3-stage cp.async pipeline (dyn smem).
#define NKT (DIM / 32)          // 24
#define GST (128 * 40)          // elems per tile stage
#define SMEM_GEMM (6 * GST * 2) // 61440 B
__global__ void __launch_bounds__(256) gemm_bf(
        const __nv_bfloat16* __restrict__ A,
        const __nv_bfloat16* __restrict__ Wall,
        const float* __restrict__ b0, const float* __restrict__ b1,
        const float* __restrict__ b2,
        __nv_bfloat16* __restrict__ c0, __nv_bfloat16* __restrict__ c1,
        __nv_bfloat16* __restrict__ c2,
        const float* __restrict__ res, float* __restrict__ outF,
        int mode) {
    extern __shared__ __nv_bfloat16 gsm[];
    __nv_bfloat16* Asb = gsm;             // [3][128][40]
    __nv_bfloat16* Bsb = gsm + 3 * GST;   // [3][128][40]

    int nb, sel;
    if (mode == 0) { sel = blockIdx.x / 6; nb = blockIdx.x % 6; }
    else           { sel = 3;              nb = blockIdx.x; }
    const __nv_bfloat16* W = Wall + (size_t)sel * DIM * DIM;
    const float* bias = mode == 0 ? (sel == 0 ? b0 : sel == 1 ? b1 : b2) : b0;
    __nv_bfloat16* Cb = sel == 0 ? c0 : sel == 1 ? c1 : c2;

    int bm0 = blockIdx.y * 128, bn0 = nb * 128;
    int tid = threadIdx.x, lane = tid & 31, wid = tid >> 5;
    int g = lane >> 2, tq = lane & 3;
    int wm = (wid >> 2) * 64, wn = (wid & 3) * 32;

    int lr = tid >> 1, lk = (tid & 1) * 16;
    const __nv_bfloat16* Ag = A + (size_t)(bm0 + lr) * DIM + lk;
    const __nv_bfloat16* Wg = W + (size_t)(bn0 + lr) * DIM + lk;

    float acc[4][4][4] = {};

    // prefetch stages 0,1
    #pragma unroll
    for (int p = 0; p < 2; p++) {
        __nv_bfloat16* as = Asb + p * GST + lr * 40 + lk;
        __nv_bfloat16* bs = Bsb + p * GST + lr * 40 + lk;
        cp16(as,     Ag + p * 32);
        cp16(as + 8, Ag + p * 32 + 8);
        cp16(bs,     Wg + p * 32);
        cp16(bs + 8, Wg + p * 32 + 8);
        cp_commit();
    }

    int st = 0, stw = 2;
    for (int kt = 0; kt < NKT; kt++) {
        if (kt + 2 < NKT) {
            __nv_bfloat16* as = Asb + stw * GST + lr * 40 + lk;
            __nv_bfloat16* bs = Bsb + stw * GST + lr * 40 + lk;
            const __nv_bfloat16* ag = Ag + (kt + 2) * 32;
            const __nv_bfloat16* wg = Wg + (kt + 2) * 32;
            cp16(as,     ag);
            cp16(as + 8, ag + 8);
            cp16(bs,     wg);
            cp16(bs + 8, wg + 8);
            cp_commit();
            asm volatile("cp.async.wait_group 2;\n");
        } else if (kt + 1 < NKT) {
            asm volatile("cp.async.wait_group 1;\n");
        } else {
            asm volatile("cp.async.wait_group 0;\n");
        }
        __syncthreads();

        uint32_t aA = saddr(Asb + st * GST + (wm + (lane & 15)) * 40
                            + (lane >> 4) * 8);
        uint32_t aB = saddr(Bsb + st * GST
                            + (wn + (lane & 7) + ((lane >> 4) & 1) * 8) * 40
                            + ((lane >> 3) & 1) * 8);
        #pragma unroll
        for (int ks = 0; ks < 2; ks++) {
            uint32_t a[4][4], b[2][4];
            #pragma unroll
            for (int mt = 0; mt < 4; mt++)
                ldsm4(a[mt], aA + mt * (16 * 80) + ks * 32);
            #pragma unroll
            for (int nt = 0; nt < 2; nt++)
                ldsm4(b[nt], aB + nt * (16 * 80) + ks * 32);
            #pragma unroll
            for (int mt = 0; mt < 4; mt++) {
                #pragma unroll
                for (int nt = 0; nt < 2; nt++) {
                    mma16816(acc[mt][2 * nt],     a[mt], b[nt]);
                    mma16816(acc[mt][2 * nt + 1], a[mt], b[nt] + 2);
                }
            }
        }
        __syncthreads();
        st = st == 2 ? 0 : st + 1;
        stw = stw == 2 ? 0 : stw + 1;
    }

    #pragma unroll
    for (int mt = 0; mt < 4; mt++) {
        int row = bm0 + wm + 16 * mt + g;
        #pragma unroll
        for (int j = 0; j < 4; j++) {
            int col = bn0 + wn + 8 * j + 2 * tq;
            float bx = bias[col], by = bias[col + 1];
            size_t o0 = (size_t)row * DIM + col;
            size_t o1 = (size_t)(row + 8) * DIM + col;
            if (mode == 0) {
                *(uint32_t*)(Cb + o0) = packbf(acc[mt][j][0] + bx,
                                               acc[mt][j][1] + by);
                *(uint32_t*)(Cb + o1) = packbf(acc[mt][j][2] + bx,
                                               acc[mt][j][3] + by);
            } else {
                float2 e0 = *(const float2*)(res + o0);
                float2 e1 = *(const float2*)(res + o1);
                *(float2*)(outF + o0) = make_float2(acc[mt][j][0] + bx + e0.x,
                                                    acc[mt][j][1] + by + e0.y);
                *(float2*)(outF + o1) = make_float2(acc[mt][j][2] + bx + e1.x,
                                                    acc[mt][j][3] + by + e1.y);
            }
        }
    }
}

// ---------------- bf16 flash attention: 256 thr, 128-row Q tile -------------
// grid (SEQ/128, NH, BATCH) = (8,12,4). 8 warps, warp owns 16 Q rows.
// dyn smem: sQ[128*72] | sK[2][64*72] | sV[2][64*72] | sP[128*72] = 73728 B
#define KTILE 4608              // 64*72 elems
#define QTILE 9216              // 128*72 elems
#define SMEM_ATTN ((QTILE + 2*KTILE + 2*KTILE + QTILE) * 2)
__global__ void __launch_bounds__(256) attn_tc(const __nv_bfloat16* __restrict__ Q,
                                               const __nv_bfloat16* __restrict__ K,
                                               const __nv_bfloat16* __restrict__ V,
                                               __nv_bfloat16* __restrict__ O) {
    extern __shared__ __nv_bfloat16 smb[];
    __nv_bfloat16* sQ = smb;                       // 128 x 72
    __nv_bfloat16* sK = smb + QTILE;               // 2 x 64 x 72
    __nv_bfloat16* sV = smb + QTILE + 2 * KTILE;   // 2 x 64 x 72
    __nv_bfloat16* sP = smb + QTILE + 4 * KTILE;   // 128 x 72

    int qt = blockIdx.x, h = blockIdx.y, b = blockIdx.z;
    int tid = threadIdx.x, lane = tid & 31, wid = tid >> 5;
    int g = lane >> 2, tq = lane & 3;
    int m0 = wid * 16;

    // Q loader: 128 rows, each thread one row-half
    int qlr = tid >> 1, qlk = (tid & 1) * 32;
    // K/V loader: 64 rows, each thread 16 elems
    int klr = tid >> 2, klk = (tid & 3) * 16;

    const __nv_bfloat16* Kg = K + (size_t)(b * SEQ + klr) * DIM + h * DH + klk;
    const __nv_bfloat16* Vg = V + (size_t)(b * SEQ + klr) * DIM + h * DH + klk;

    // Q tile (plain copy; first __syncthreads covers it)
    {
        const uint4* qp = (const uint4*)(Q + (size_t)(b * SEQ + qt * 128 + qlr) * DIM
                                           + h * DH + qlk);
        uint4* dq = (uint4*)&sQ[qlr * 72 + qlk];
        #pragma unroll
        for (int u = 0; u < 4; u++) dq[u] = qp[u];
    }

    // prefetch K/V tile 0 into stage 0
    cp16(&sK[klr * 72 + klk],     Kg);
    cp16(&sK[klr * 72 + klk + 8], Kg + 8);
    cp16(&sV[klr * 72 + klk],     Vg);
    cp16(&sV[klr * 72 + klk + 8], Vg + 8);
    cp_commit();

    uint32_t aQ = saddr(&sQ[(m0 + (lane & 15)) * 72 + (lane >> 4) * 8]);
    uint32_t aP = saddr(&sP[(m0 + (lane & 15)) * 72 + (lane >> 4) * 8]);
    uint32_t aK0 = saddr(&sK[((lane & 7) + ((lane >> 4) & 1) * 8) * 72
                             + ((lane >> 3) & 1) * 8]);
    uint32_t aV0 = saddr(&sV[((lane & 7) + ((lane >> 3) & 1) * 8) * 72
                             + (lane >> 4) * 8]);

    float m0r = -1e30f, m1r = -1e30f, l0r = 0.f, l1r = 0.f;
    float o[8][4] = {};

    for (int kt = 0; kt < SEQ / 64; kt++) {
        int s = kt & 1;
        if (kt + 1 < SEQ / 64) {
            int so = (s ^ 1) * KTILE;
            const __nv_bfloat16* kg = Kg + (size_t)(kt + 1) * 64 * DIM;
            const __nv_bfloat16* vg = Vg + (size_t)(kt + 1) * 64 * DIM;
            cp16(&sK[so + klr * 72 + klk],     kg);
            cp16(&sK[so + klr * 72 + klk + 8], kg + 8);
            cp16(&sV[so + klr * 72 + klk],     vg);
            cp16(&sV[so + klr * 72 + klk + 8], vg + 8);
            cp_commit();
            asm volatile("cp.async.wait_group 1;\n");
        } else {
            asm volatile("cp.async.wait_group 0;\n");
        }
        __syncthreads();

        uint32_t aK = aK0 + s * (KTILE * 2);
        uint32_t aV = aV0 + s * (KTILE * 2);

        // S = Q K^T (warp's 16 rows x 64 keys)
        float sc[8][4] = {};
        #pragma unroll
        for (int ks = 0; ks < 4; ks++) {
            uint32_t a[4];
            ldsm4(a, aQ + ks * 32);
            #pragma unroll
            for (int j2 = 0; j2 < 4; j2++) {
                uint32_t bb[4];
                ldsm4(bb, aK + j2 * (16 * 144) + ks * 32);
                mma16816(sc[2 * j2],     a, bb);
                mma16816(sc[2 * j2 + 1], a, bb + 2);
            }
        }
        #pragma unroll
        for (int j = 0; j < 8; j++)
            #pragma unroll
            for (int c = 0; c < 4; c++) sc[j][c] *= SCALE_ATT;

        // online softmax in registers (rows g and g+8)
        float mx0 = -1e30f, mx1 = -1e30f;
        #pragma unroll
        for (int j = 0; j < 8; j++) {
            mx0 = fmaxf(mx0, fmaxf(sc[j][0], sc[j][1]));
            mx1 = fmaxf(mx1, fmaxf(sc[j][2], sc[j][3]));
        }
        mx0 = fmaxf(mx0, __shfl_xor_sync(0xffffffffu, mx0, 1));
        mx0 = fmaxf(mx0, __shfl_xor_sync(0xffffffffu, mx0, 2));
        mx1 = fmaxf(mx1, __shfl_xor_sync(0xffffffffu, mx1, 1));
        mx1 = fmaxf(mx1, __shfl_xor_sync(0xffffffffu, mx1, 2));
        float mn0 = fmaxf(m0r, mx0), mn1 = fmaxf(m1r, mx1);
        float al0 = __expf(m0r - mn0), al1 = __expf(m1r - mn1);
        float ls0 = 0.f, ls1 = 0.f;
        #pragma unroll
        for (int j = 0; j < 8; j++) {
            sc[j][0] = __expf(sc[j][0] - mn0); ls0 += sc[j][0];
            sc[j][1] = __expf(sc[j][1] - mn0); ls0 += sc[j][1];
            sc[j][2] = __expf(sc[j][2] - mn1); ls1 += sc[j][2];
            sc[j][3] = __expf(sc[j][3] - mn1); ls1 += sc[j][3];
        }
        ls0 += __shfl_xor_sync(0xffffffffu, ls0, 1);
        ls0 += __shfl_xor_sync(0xffffffffu, ls0, 2);
        ls1 += __shfl_xor_sync(0xffffffffu, ls1, 1);
        ls1 += __shfl_xor_sync(0xffffffffu, ls1, 2);
        l0r = l0r * al0 + ls0;  m0r = mn0;
        l1r = l1r * al1 + ls1;  m1r = mn1;
        #pragma unroll
        for (int j = 0; j < 8; j++) {
            o[j][0] *= al0; o[j][1] *= al0;
            o[j][2] *= al1; o[j][3] *= al1;
        }

        // P -> per-warp smem (bf16)
        {
            uint32_t* p0 = (uint32_t*)&sP[(m0 + g) * 72];
            uint32_t* p1 = (uint32_t*)&sP[(m0 + g + 8) * 72];
            #pragma unroll
            for (int j = 0; j < 8; j++) {
                p0[4 * j + tq] = packbf(sc[j][0], sc[j][1]);
                p1[4 * j + tq] = packbf(sc[j][2], sc[j][3]);
            }
        }
        __syncwarp();

        // O += P V  (V via ldmatrix.trans)
        #pragma unroll
        for (int ks = 0; ks < 4; ks++) {
            uint32_t a[4];
            ldsm4(a, aP + ks * 32);
            #pragma unroll
            for (int j2 = 0; j2 < 4; j2++) {
                uint32_t bb[4];
                ldsm4t(bb, aV + ks * (16 * 144) + j2 * 32);
                mma16816(o[2 * j2],     a, bb);
                mma16816(o[2 * j2 + 1], a, bb + 2);
            }
        }
        __syncthreads();   // sK/sV stage reuse fence
    }

    float inv0 = 1.f / l0r, inv1 = 1.f / l1r;
    int row0 = b * SEQ + qt * 128 + m0 + g;
    #pragma unroll
    for (int j = 0; j < 8; j++) {
        int col = h * DH + 8 * j + 2 * tq;
        *(uint32_t*)(O + (size_t)row0 * DIM + col) =
            packbf(o[j][0] * inv0, o[j][1] * inv0);
        *(uint32_t*)(O + (size_t)(row0 + 8) * DIM + col) =
            packbf(o[j][2] * inv1, o[j][3] * inv1);
    }
}

// ---------------- launch ----------------
extern "C" void kernel_launch(void* const* d_in, const int* in_sizes, int n_in,
                              void* d_out, int out_size) {
    const float* x  = (const float*)d_in[0];
    const float* qw = (const float*)d_in[1];
    const float* kw = (const float*)d_in[2];
    const float* vw = (const float*)d_in[3];
    const float* qb = (const float*)d_in[4];
    const float* kb = (const float*)d_in[5];
    const float* vb = (const float*)d_in[6];
    const float* pw = (const float*)d_in[7];
    const float* pb = (const float*)d_in[8];
    float* out = (float*)d_out;

    __nv_bfloat16 *xn, *q, *k, *v, *att, *wb;
    cudaGetSymbolAddress((void**)&xn,  g_xn);
    cudaGetSymbolAddress((void**)&q,   g_q);
    cudaGetSymbolAddress((void**)&k,   g_k);
    cudaGetSymbolAddress((void**)&v,   g_v);
    cudaGetSymbolAddress((void**)&att, g_att);
    cudaGetSymbolAddress((void**)&wb,  g_wb);

    cudaFuncSetAttribute(attn_tc,
                         cudaFuncAttributeMaxDynamicSharedMemorySize, SMEM_ATTN);
    cudaFuncSetAttribute(gemm_bf,
                         cudaFuncAttributeMaxDynamicSharedMemorySize, SMEM_GEMM);

    cvt_w<<<dim3(DIM * DIM / 1024, 4), 256>>>(qw, kw, vw, pw, wb);
    ln_kernel<<<ROWS, 384>>>(x, xn);

    // QKV: 18 x 32 blocks (sel = x/6)
    gemm_bf<<<dim3(18, 32), 256, SMEM_GEMM>>>(xn, wb, qb, kb, vb, q, k, v,
                                              nullptr, nullptr, 0);

    attn_tc<<<dim3(SEQ / 128, NH, BATCH), 256, SMEM_ATTN>>>(q, k, v, att);

    // proj: 6 x 32 blocks, fp32 out + bias + residual
    gemm_bf<<<dim3(6, 32), 256, SMEM_GEMM>>>(att, wb, pb, nullptr, nullptr,
                                             nullptr, nullptr, nullptr, x, out, 1);
}

// round 7
// speedup vs baseline: 9.9154x; 1.0864x over previous
#include <cuda_runtime.h>
#include <cuda_bf16.h>
#include <cstdint>

#define DIM 768
#define NH 12
#define DH 64
#define BATCH 4
#define SEQ 1024
#define ROWS (BATCH*SEQ)            // 4096
#define QSCALE 0.18033688011112042f // 0.125 * log2(e), folded into Q epilogue

// ---------------- scratch ----------------
__device__ __nv_bfloat16 g_xn [ROWS*DIM];
__device__ __nv_bfloat16 g_q  [ROWS*DIM];
__device__ __nv_bfloat16 g_k  [ROWS*DIM];
__device__ __nv_bfloat16 g_v  [ROWS*DIM];
__device__ __nv_bfloat16 g_att[ROWS*DIM];
__device__ __nv_bfloat16 g_wb [4 * DIM * DIM];   // bf16 weights: q,k,v,proj

// ---------------- helpers ----------------
__device__ __forceinline__ uint32_t saddr(const void* p) {
    return (uint32_t)__cvta_generic_to_shared(p);
}
__device__ __forceinline__ void cp16(void* s, const void* g) {
    asm volatile("cp.async.cg.shared.global [%0], [%1], 16;\n"
                 :: "r"(saddr(s)), "l"(g));
}
__device__ __forceinline__ void cp_commit() {
    asm volatile("cp.async.commit_group;\n");
}
__device__ __forceinline__ void ldsm4(uint32_t* r, uint32_t a) {
    asm volatile("ldmatrix.sync.aligned.m8n8.x4.shared.b16 {%0,%1,%2,%3}, [%4];"
                 : "=r"(r[0]), "=r"(r[1]), "=r"(r[2]), "=r"(r[3]) : "r"(a));
}
__device__ __forceinline__ void ldsm4t(uint32_t* r, uint32_t a) {
    asm volatile("ldmatrix.sync.aligned.m8n8.x4.trans.shared.b16 {%0,%1,%2,%3}, [%4];"
                 : "=r"(r[0]), "=r"(r[1]), "=r"(r[2]), "=r"(r[3]) : "r"(a));
}
__device__ __forceinline__ void mma16816(float* d, const uint32_t* a, const uint32_t* b) {
    asm volatile("mma.sync.aligned.m16n8k16.row.col.f32.bf16.bf16.f32 "
        "{%0,%1,%2,%3}, {%4,%5,%6,%7}, {%8,%9}, {%0,%1,%2,%3};\n"
        : "+f"(d[0]), "+f"(d[1]), "+f"(d[2]), "+f"(d[3])
        : "r"(a[0]), "r"(a[1]), "r"(a[2]), "r"(a[3]), "r"(b[0]), "r"(b[1]));
}
__device__ __forceinline__ uint32_t packbf(float lo, float hi) {
    __nv_bfloat162 h = __floats2bfloat162_rn(lo, hi);
    return *reinterpret_cast<uint32_t*>(&h);
}
__device__ __forceinline__ float ex2(float x) {
    float y;
    asm("ex2.approx.ftz.f32 %0, %1;" : "=f"(y) : "f"(x));
    return y;
}

// ---------------- weight fp32 -> bf16 ----------------
__global__ void __launch_bounds__(256) cvt_w(const float* __restrict__ s0,
                                             const float* __restrict__ s1,
                                             const float* __restrict__ s2,
                                             const float* __restrict__ s3,
                                             __nv_bfloat16* __restrict__ d) {
    int m = blockIdx.y;
    const float* s = m == 0 ? s0 : m == 1 ? s1 : m == 2 ? s2 : s3;
    __nv_bfloat16* dp = d + (size_t)m * DIM * DIM;
    int i = (blockIdx.x * 256 + threadIdx.x) * 4;
    float4 v = *(const float4*)(s + i);
    uint2 o;
    o.x = packbf(v.x, v.y);
    o.y = packbf(v.z, v.w);
    *(uint2*)(dp + i) = o;
}

// ---------------- LayerNorm (ddof=1) ----------------
__global__ void __launch_bounds__(384) ln_kernel(const float* __restrict__ x,
                                                 __nv_bfloat16* __restrict__ xn) {
    int row = blockIdx.x, t = threadIdx.x;
    float2 v = *(const float2*)(x + (size_t)row * DIM + 2 * t);
    float s  = v.x + v.y;
    float sq = v.x * v.x + v.y * v.y;
    #pragma unroll
    for (int o = 16; o; o >>= 1) {
        s  += __shfl_xor_sync(0xffffffffu, s,  o);
        sq += __shfl_xor_sync(0xffffffffu, sq, o);
    }
    __shared__ float rs[12], rq[12];
    int w = t >> 5, l = t & 31;
    if (l == 0) { rs[w] = s; rq[w] = sq; }
    __syncthreads();
    if (w == 0) {
        s  = (l < 12) ? rs[l] : 0.f;
        sq = (l < 12) ? rq[l] : 0.f;
        #pragma unroll
        for (int o = 16; o; o >>= 1) {
            s  += __shfl_xor_sync(0xffffffffu, s,  o);
            sq += __shfl_xor_sync(0xffffffffu, sq, o);
        }
        if (l == 0) { rs[0] = s; rq[0] = sq; }
    }
    __syncthreads();
    s = rs[0]; sq = rq[0];
    float mean = s * (1.f / DIM);
    float var  = (sq - (float)DIM * mean * mean) * (1.f / (DIM - 1));
    float inv  = rsqrtf(var);
    ((uint32_t*)xn)[(size_t)row * (DIM / 2) + t] =
        packbf((v.x - mean) * inv, (v.y - mean) * inv);
}

// ---------------- bf16 3-stage pipelined GEMM-NT ----------------------------
// C[M,N] = A[M,K] @ W[N,K]^T + bias (+res).  BM=128 BN=128 BK=32, 256 thr.
// mode 0: bf16 out (+bias), sel = blockIdx.x/6 picks q/k/v; q output is
//         additionally scaled by QSCALE (softmax base-2 fold).
// mode 1: fp32 out + bias + residual.
#define NKT (DIM / 32)          // 24
#define GST (128 * 40)          // elems per tile stage
#define SMEM_GEMM (6 * GST * 2) // 61440 B
__global__ void __launch_bounds__(256) gemm_bf(
        const __nv_bfloat16* __restrict__ A,
        const __nv_bfloat16* __restrict__ Wall,
        const float* __restrict__ b0, const float* __restrict__ b1,
        const float* __restrict__ b2,
        __nv_bfloat16* __restrict__ c0, __nv_bfloat16* __restrict__ c1,
        __nv_bfloat16* __restrict__ c2,
        const float* __restrict__ res, float* __restrict__ outF,
        int mode) {
    extern __shared__ __nv_bfloat16 gsm[];
    __nv_bfloat16* Asb = gsm;             // [3][128][40]
    __nv_bfloat16* Bsb = gsm + 3 * GST;   // [3][128][40]

    int nb, sel;
    if (mode == 0) { sel = blockIdx.x / 6; nb = blockIdx.x % 6; }
    else           { sel = 3;              nb = blockIdx.x; }
    const __nv_bfloat16* W = Wall + (size_t)sel * DIM * DIM;
    const float* bias = mode == 0 ? (sel == 0 ? b0 : sel == 1 ? b1 : b2) : b0;
    __nv_bfloat16* Cb = sel == 0 ? c0 : sel == 1 ? c1 : c2;
    float oscale = (mode == 0 && sel == 0) ? QSCALE : 1.0f;

    int bm0 = blockIdx.y * 128, bn0 = nb * 128;
    int tid = threadIdx.x, lane = tid & 31, wid = tid >> 5;
    int g = lane >> 2, tq = lane & 3;
    int wm = (wid >> 2) * 64, wn = (wid & 3) * 32;

    int lr = tid >> 1, lk = (tid & 1) * 16;
    const __nv_bfloat16* Ag = A + (size_t)(bm0 + lr) * DIM + lk;
    const __nv_bfloat16* Wg = W + (size_t)(bn0 + lr) * DIM + lk;

    float acc[4][4][4] = {};

    // prefetch stages 0,1
    #pragma unroll
    for (int p = 0; p < 2; p++) {
        __nv_bfloat16* as = Asb + p * GST + lr * 40 + lk;
        __nv_bfloat16* bs = Bsb + p * GST + lr * 40 + lk;
        cp16(as,     Ag + p * 32);
        cp16(as + 8, Ag + p * 32 + 8);
        cp16(bs,     Wg + p * 32);
        cp16(bs + 8, Wg + p * 32 + 8);
        cp_commit();
    }

    int st = 0, stw = 2;
    for (int kt = 0; kt < NKT; kt++) {
        if (kt + 2 < NKT) {
            __nv_bfloat16* as = Asb + stw * GST + lr * 40 + lk;
            __nv_bfloat16* bs = Bsb + stw * GST + lr * 40 + lk;
            const __nv_bfloat16* ag = Ag + (kt + 2) * 32;
            const __nv_bfloat16* wg = Wg + (kt + 2) * 32;
            cp16(as,     ag);
            cp16(as + 8, ag + 8);
            cp16(bs,     wg);
            cp16(bs + 8, wg + 8);
            cp_commit();
            asm volatile("cp.async.wait_group 2;\n");
        } else if (kt + 1 < NKT) {
            asm volatile("cp.async.wait_group 1;\n");
        } else {
            asm volatile("cp.async.wait_group 0;\n");
        }
        __syncthreads();

        uint32_t aA = saddr(Asb + st * GST + (wm + (lane & 15)) * 40
                            + (lane >> 4) * 8);
        uint32_t aB = saddr(Bsb + st * GST
                            + (wn + (lane & 7) + ((lane >> 4) & 1) * 8) * 40
                            + ((lane >> 3) & 1) * 8);
        #pragma unroll
        for (int ks = 0; ks < 2; ks++) {
            uint32_t a[4][4], b[2][4];
            #pragma unroll
            for (int mt = 0; mt < 4; mt++)
                ldsm4(a[mt], aA + mt * (16 * 80) + ks * 32);
            #pragma unroll
            for (int nt = 0; nt < 2; nt++)
                ldsm4(b[nt], aB + nt * (16 * 80) + ks * 32);
            #pragma unroll
            for (int mt = 0; mt < 4; mt++) {
                #pragma unroll
                for (int nt = 0; nt < 2; nt++) {
                    mma16816(acc[mt][2 * nt],     a[mt], b[nt]);
                    mma16816(acc[mt][2 * nt + 1], a[mt], b[nt] + 2);
                }
            }
        }
        __syncthreads();
        st = st == 2 ? 0 : st + 1;
        stw = stw == 2 ? 0 : stw + 1;
    }

    #pragma unroll
    for (int mt = 0; mt < 4; mt++) {
        int row = bm0 + wm + 16 * mt + g;
        #pragma unroll
        for (int j = 0; j < 4; j++) {
            int col = bn0 + wn + 8 * j + 2 * tq;
            float bx = bias[col], by = bias[col + 1];
            size_t o0 = (size_t)row * DIM + col;
            size_t o1 = (size_t)(row + 8) * DIM + col;
            if (mode == 0) {
                *(uint32_t*)(Cb + o0) = packbf((acc[mt][j][0] + bx) * oscale,
                                               (acc[mt][j][1] + by) * oscale);
                *(uint32_t*)(Cb + o1) = packbf((acc[mt][j][2] + bx) * oscale,
                                               (acc[mt][j][3] + by) * oscale);
            } else {
                float2 e0 = *(const float2*)(res + o0);
                float2 e1 = *(const float2*)(res + o1);
                *(float2*)(outF + o0) = make_float2(acc[mt][j][0] + bx + e0.x,
                                                    acc[mt][j][1] + by + e0.y);
                *(float2*)(outF + o1) = make_float2(acc[mt][j][2] + bx + e1.x,
                                                    acc[mt][j][3] + by + e1.y);
            }
        }
    }
}

// ---------------- bf16 flash attention: P in registers ----------------------
// grid (SEQ/128, NH, BATCH) = (8,12,4). 256 thr, 8 warps x 16 Q rows.
// dyn smem: sQ[128*72] | sK[2][64*72] | sV[2][64*72] = 55296 B
// Q pre-scaled by QSCALE in GEMM; softmax in base-2 (ex2.approx).
#define KTILE 4608              // 64*72 elems
#define QTILE 9216              // 128*72 elems
#define SMEM_ATTN ((QTILE + 4 * KTILE) * 2)
__global__ void __launch_bounds__(256) attn_tc(const __nv_bfloat16* __restrict__ Q,
                                               const __nv_bfloat16* __restrict__ K,
                                               const __nv_bfloat16* __restrict__ V,
                                               __nv_bfloat16* __restrict__ O) {
    extern __shared__ __nv_bfloat16 smb[];
    __nv_bfloat16* sQ = smb;                       // 128 x 72
    __nv_bfloat16* sK = smb + QTILE;               // 2 x 64 x 72
    __nv_bfloat16* sV = smb + QTILE + 2 * KTILE;   // 2 x 64 x 72

    int qt = blockIdx.x, h = blockIdx.y, b = blockIdx.z;
    int tid = threadIdx.x, lane = tid & 31, wid = tid >> 5;
    int g = lane >> 2, tq = lane & 3;
    int m0 = wid * 16;

    int qlr = tid >> 1, qlk = (tid & 1) * 32;   // Q loader
    int klr = tid >> 2, klk = (tid & 3) * 16;   // K/V loader

    const __nv_bfloat16* Kg = K + (size_t)(b * SEQ + klr) * DIM + h * DH + klk;
    const __nv_bfloat16* Vg = V + (size_t)(b * SEQ + klr) * DIM + h * DH + klk;

    // Q tile copy (already scaled by QSCALE in GEMM)
    {
        const uint4* qp = (const uint4*)(Q + (size_t)(b * SEQ + qt * 128 + qlr) * DIM
                                           + h * DH + qlk);
        uint4* dq = (uint4*)&sQ[qlr * 72 + qlk];
        #pragma unroll
        for (int u = 0; u < 4; u++) dq[u] = qp[u];
    }

    // prefetch K/V tile 0 into stage 0
    cp16(&sK[klr * 72 + klk],     Kg);
    cp16(&sK[klr * 72 + klk + 8], Kg + 8);
    cp16(&sV[klr * 72 + klk],     Vg);
    cp16(&sV[klr * 72 + klk + 8], Vg + 8);
    cp_commit();

    uint32_t aQ = saddr(&sQ[(m0 + (lane & 15)) * 72 + (lane >> 4) * 8]);
    uint32_t aK0 = saddr(&sK[((lane & 7) + ((lane >> 4) & 1) * 8) * 72
                             + ((lane >> 3) & 1) * 8]);
    uint32_t aV0 = saddr(&sV[((lane & 7) + ((lane >> 3) & 1) * 8) * 72
                             + (lane >> 4) * 8]);

    __syncthreads();   // Q tile visible to all warps

    // hoist Q fragments into registers (reused all iterations)
    uint32_t qf[4][4];
    #pragma unroll
    for (int ks = 0; ks < 4; ks++) ldsm4(qf[ks], aQ + ks * 32);

    float m0r = -1e30f, m1r = -1e30f, l0r = 0.f, l1r = 0.f;
    float o[8][4] = {};

    for (int kt = 0; kt < SEQ / 64; kt++) {
        int s = kt & 1;
        asm volatile("cp.async.wait_group 0;\n");
        __syncthreads();   // stage s ready; stage s^1 readers (iter kt-1) done
        if (kt + 1 < SEQ / 64) {
            int so = (s ^ 1) * KTILE;
            const __nv_bfloat16* kg = Kg + (size_t)(kt + 1) * 64 * DIM;
            const __nv_bfloat16* vg = Vg + (size_t)(kt + 1) * 64 * DIM;
            cp16(&sK[so + klr * 72 + klk],     kg);
            cp16(&sK[so + klr * 72 + klk + 8], kg + 8);
            cp16(&sV[so + klr * 72 + klk],     vg);
            cp16(&sV[so + klr * 72 + klk + 8], vg + 8);
            cp_commit();
        }

        uint32_t aK = aK0 + s * (KTILE * 2);
        uint32_t aV = aV0 + s * (KTILE * 2);

        // S = Q K^T (warp's 16 rows x 64 keys); sc[j] = key cols 8j..8j+7
        float sc[8][4] = {};
        #pragma unroll
        for (int ks = 0; ks < 4; ks++) {
            #pragma unroll
            for (int j2 = 0; j2 < 4; j2++) {
                uint32_t bb[4];
                ldsm4(bb, aK + j2 * (16 * 144) + ks * 32);
                mma16816(sc[2 * j2],     qf[ks], bb);
                mma16816(sc[2 * j2 + 1], qf[ks], bb + 2);
            }
        }

        // online softmax, base-2 domain (Q pre-scaled by 0.125*log2e)
        float mx0 = -1e30f, mx1 = -1e30f;
        #pragma unroll
        for (int j = 0; j < 8; j++) {
            mx0 = fmaxf(mx0, fmaxf(sc[j][0], sc[j][1]));
            mx1 = fmaxf(mx1, fmaxf(sc[j][2], sc[j][3]));
        }
        mx0 = fmaxf(mx0, __shfl_xor_sync(0xffffffffu, mx0, 1));
        mx0 = fmaxf(mx0, __shfl_xor_sync(0xffffffffu, mx0, 2));
        mx1 = fmaxf(mx1, __shfl_xor_sync(0xffffffffu, mx1, 1));
        mx1 = fmaxf(mx1, __shfl_xor_sync(0xffffffffu, mx1, 2));
        float mn0 = fmaxf(m0r, mx0), mn1 = fmaxf(m1r, mx1);
        float al0 = ex2(m0r - mn0), al1 = ex2(m1r - mn1);
        float ls0 = 0.f, ls1 = 0.f;
        #pragma unroll
        for (int j = 0; j < 8; j++) {
            sc[j][0] = ex2(sc[j][0] - mn0); ls0 += sc[j][0];
            sc[j][1] = ex2(sc[j][1] - mn0); ls0 += sc[j][1];
            sc[j][2] = ex2(sc[j][2] - mn1); ls1 += sc[j][2];
            sc[j][3] = ex2(sc[j][3] - mn1); ls1 += sc[j][3];
        }
        ls0 += __shfl_xor_sync(0xffffffffu, ls0, 1);
        ls0 += __shfl_xor_sync(0xffffffffu, ls0, 2);
        ls1 += __shfl_xor_sync(0xffffffffu, ls1, 1);
        ls1 += __shfl_xor_sync(0xffffffffu, ls1, 2);
        l0r = l0r * al0 + ls0;  m0r = mn0;
        l1r = l1r * al1 + ls1;  m1r = mn1;
        #pragma unroll
        for (int j = 0; j < 8; j++) {
            o[j][0] *= al0; o[j][1] *= al0;
            o[j][2] *= al1; o[j][3] *= al1;
        }

        // O += P V : P packed straight from S fragments (no smem round-trip).
        // C-frag (m16n8) pairs == A-frag (m16n8k16) halves:
        //   a0=(row g, k=16ks+2tq,+1)  a1=(row g+8, same)
        //   a2=(row g, k=16ks+8+2tq,+1) a3=(row g+8, same)
        #pragma unroll
        for (int ks = 0; ks < 4; ks++) {
            uint32_t a[4];
            a[0] = packbf(sc[2 * ks][0],     sc[2 * ks][1]);
            a[1] = packbf(sc[2 * ks][2],     sc[2 * ks][3]);
            a[2] = packbf(sc[2 * ks + 1][0], sc[2 * ks + 1][1]);
            a[3] = packbf(sc[2 * ks + 1][2], sc[2 * ks + 1][3]);
            #pragma unroll
            for (int j2 = 0; j2 < 4; j2++) {
                uint32_t bb[4];
                ldsm4t(bb, aV + ks * (16 * 144) + j2 * 32);
                mma16816(o[2 * j2],     a, bb);
                mma16816(o[2 * j2 + 1], a, bb + 2);
            }
        }
    }

    float inv0 = 1.f / l0r, inv1 = 1.f / l1r;
    int row0 = b * SEQ + qt * 128 + m0 + g;
    #pragma unroll
    for (int j = 0; j < 8; j++) {
        int col = h * DH + 8 * j + 2 * tq;
        *(uint32_t*)(O + (size_t)row0 * DIM + col) =
            packbf(o[j][0] * inv0, o[j][1] * inv0);
        *(uint32_t*)(O + (size_t)(row0 + 8) * DIM + col) =
            packbf(o[j][2] * inv1, o[j][3] * inv1);
    }
}

// ---------------- launch ----------------
extern "C" void kernel_launch(void* const* d_in, const int* in_sizes, int n_in,
                              void* d_out, int out_size) {
    const float* x  = (const float*)d_in[0];
    const float* qw = (const float*)d_in[1];
    const float* kw = (const float*)d_in[2];
    const float* vw = (const float*)d_in[3];
    const float* qb = (const float*)d_in[4];
    const float* kb = (const float*)d_in[5];
    const float* vb = (const float*)d_in[6];
    const float* pw = (const float*)d_in[7];
    const float* pb = (const float*)d_in[8];
    float* out = (float*)d_out;

    __nv_bfloat16 *xn, *q, *k, *v, *att, *wb;
    cudaGetSymbolAddress((void**)&xn,  g_xn);
    cudaGetSymbolAddress((void**)&q,   g_q);
    cudaGetSymbolAddress((void**)&k,   g_k);
    cudaGetSymbolAddress((void**)&v,   g_v);
    cudaGetSymbolAddress((void**)&att, g_att);
    cudaGetSymbolAddress((void**)&wb,  g_wb);

    cudaFuncSetAttribute(attn_tc,
                         cudaFuncAttributeMaxDynamicSharedMemorySize, SMEM_ATTN);
    cudaFuncSetAttribute(gemm_bf,
                         cudaFuncAttributeMaxDynamicSharedMemorySize, SMEM_GEMM);

    cvt_w<<<dim3(DIM * DIM / 1024, 4), 256>>>(qw, kw, vw, pw, wb);
    ln_kernel<<<ROWS, 384>>>(x, xn);

    // QKV: 18 x 32 blocks (sel = x/6); q output pre-scaled by QSCALE
    gemm_bf<<<dim3(18, 32), 256, SMEM_GEMM>>>(xn, wb, qb, kb, vb, q, k, v,
                                              nullptr, nullptr, 0);

    attn_tc<<<dim3(SEQ / 128, NH, BATCH), 256, SMEM_ATTN>>>(q, k, v, att);

    // proj: 6 x 32 blocks, fp32 out + bias + residual
    gemm_bf<<<dim3(6, 32), 256, SMEM_GEMM>>>(att, wb, pb, nullptr, nullptr,
                                             nullptr, nullptr, nullptr, x, out, 1);
}